// round 1
// baseline (speedup 1.0000x reference)
#include <cuda_runtime.h>
#include <math.h>

// ---------------- problem constants ----------------
#define NTOK 1024
#define DMOD 2048
#define NHEAD 8
#define DH 256
#define NLAY 3
#define MM 16
#define KSEL 8
#define DFFN 2048
#define DECH 1024
#define NCLS1 35

// ---------------- scratch (static device memory; no allocs) ----------------
static constexpr size_t ND_ = (size_t)NTOK * DMOD;           // 2,097,152 floats
static constexpr size_t OFF_SFEAT = 0;
static constexpr size_t OFF_QH    = 1 * ND_;
static constexpr size_t OFF_KH    = 2 * ND_;
static constexpr size_t OFF_VH    = 3 * ND_;
static constexpr size_t OFF_O     = 4 * ND_;
static constexpr size_t OFF_P     = 5 * ND_;
static constexpr size_t OFF_X     = 6 * ND_;
static constexpr size_t OFF_F     = 7 * ND_;   // N x DFF (same size)
static constexpr size_t OFF_F2    = 8 * ND_;
static constexpr size_t OFF_C1    = 9 * ND_;
static constexpr size_t OFF_C2    = 10 * ND_;
static constexpr size_t OFF_ATT   = 11 * ND_;                 // H*N*N = 8M floats
static constexpr size_t OFF_HD    = OFF_ATT + (size_t)NHEAD * NTOK * NTOK;
static constexpr size_t OFF_HBN   = OFF_HD + (size_t)NTOK * DECH;
static constexpr size_t SCR_FLOATS = OFF_HBN + (size_t)NTOK * DECH;

__device__ float g_scratch[SCR_FLOATS];

// ---------------- reductions ----------------
__device__ __forceinline__ float warpSum(float v) {
#pragma unroll
    for (int o = 16; o; o >>= 1) v += __shfl_down_sync(0xffffffffu, v, o);
    return v;
}
__device__ __forceinline__ float warpMax(float v) {
#pragma unroll
    for (int o = 16; o; o >>= 1) v = fmaxf(v, __shfl_down_sync(0xffffffffu, v, o));
    return v;
}
// valid on thread 0 only
__device__ float blockSum(float v) {
    __shared__ float s[8];
    int lane = threadIdx.x & 31, w = threadIdx.x >> 5;
    v = warpSum(v);
    if (lane == 0) s[w] = v;
    __syncthreads();
    float r = 0.f;
    if (w == 0) { r = (lane < 8) ? s[lane] : 0.f; r = warpSum(r); }
    __syncthreads();
    return r;
}
__device__ float blockMax(float v) {
    __shared__ float s[8];
    int lane = threadIdx.x & 31, w = threadIdx.x >> 5;
    v = warpMax(v);
    if (lane == 0) s[w] = v;
    __syncthreads();
    float r = -1e30f;
    if (w == 0) { r = (lane < 8) ? s[lane] : -1e30f; r = warpMax(r); }
    __syncthreads();
    return r;
}

// ---------------- positional encoding ----------------
// pe[p, 2i]   = sin(p * exp(-2i * ln(1e4)/D))
// pe[p, 2i+1] = cos(...)
#define PECOEF (-0.008994473019508232f)   /* -ln(10000)/1024 */

// ---------------- selector: ragged gather + top-k attention mix ----------------
__global__ void selector_k(const float* __restrict__ feat, const int* __restrict__ fid,
                           const int* __restrict__ mn, float* __restrict__ sf) {
    int n = blockIdx.x, tid = threadIdx.x;
    __shared__ int nodes[MM];
    __shared__ int pos[MM];
    __shared__ float sc[MM];
    __shared__ int sel[KSEL];
    __shared__ float wgt[KSEL];

    if (tid < MM) nodes[tid] = mn[n * MM + tid];
    __syncthreads();
    if (tid == 0) {
        int p = 0, prev = fid[nodes[0]];
        pos[0] = 0;
        for (int m = 1; m < MM; m++) {
            int f = fid[nodes[m]];
            if (f != prev) { p++; prev = f; }
            pos[m] = p;
        }
    }
    __syncthreads();

    const float* fn = feat + (size_t)n * DMOD;
    float part[MM];
#pragma unroll
    for (int m = 0; m < MM; m++) part[m] = 0.f;
    for (int d = tid; d < DMOD; d += 256) {
        float fv = fn[d];
        int i = d >> 1;
        float fr = expf((float)i * PECOEF);
        bool odd = d & 1;
#pragma unroll
        for (int m = 0; m < MM; m++) {
            float ang = (float)pos[m] * fr;
            float pev = odd ? cosf(ang) : sinf(ang);
            part[m] += fv * (feat[(size_t)nodes[m] * DMOD + d] + pev);
        }
    }
    const float scale = 0.022097086912079608f; // 1/sqrt(2048)
    for (int m = 0; m < MM; m++) {
        float ts = blockSum(part[m]);
        if (tid == 0) sc[m] = ts * scale;
    }
    __syncthreads();

    if (tid == 0) {
        unsigned used = 0;
        float tv[KSEL];
        for (int k = 0; k < KSEL; k++) {
            float best = -1e30f; int bi = 0;
            for (int m = 0; m < MM; m++)
                if (!((used >> m) & 1) && sc[m] > best) { best = sc[m]; bi = m; }
            used |= 1u << bi; sel[k] = bi; tv[k] = best;
        }
        float mx = tv[0], ssum = 0.f;
        for (int k = 0; k < KSEL; k++) { wgt[k] = expf(tv[k] - mx); ssum += wgt[k]; }
        float inv = 1.f / ssum;
        for (int k = 0; k < KSEL; k++) wgt[k] *= inv;
    }
    __syncthreads();

    float* po = sf + (size_t)n * DMOD;
    for (int d = tid; d < DMOD; d += 256) {
        int i = d >> 1;
        float fr = expf((float)i * PECOEF);
        bool odd = d & 1;
        float acc = 0.f;
#pragma unroll
        for (int k = 0; k < KSEL; k++) {
            int m = sel[k];
            float ang = (float)pos[m] * fr;
            float pev = odd ? cosf(ang) : sinf(ang);
            acc += wgt[k] * (feat[(size_t)nodes[m] * DMOD + d] + pev);
        }
        po[d] = acc;
    }
}

// ---------------- 128x128x8 SGEMM, 256 threads, 8x8 microtile ----------------
// OM=0: C[bz*sC + m*ldc + n]
// OM=1: split-head scatter  C[((n>>8)*NTOK + m)*DH + (n&255)]
// OM=2: merge-head scatter  C[m*DMOD + bz*DH + n]   (N<=DH)
template <bool TB, int OM, bool RELU>
__global__ void __launch_bounds__(256)
gemm_k(const float* __restrict__ A, const float* __restrict__ B,
       const float* __restrict__ bias, float* __restrict__ C,
       int M, int K, int N, int lda, int ldb, int ldc,
       long sA, long sB, long sC, float scale) {
    __shared__ float As[8][128];
    __shared__ float Bs[8][128];
    int bz = blockIdx.z;
    const float* Ab = A + (long)bz * sA;
    const float* Bb = B + (long)bz * sB;
    int m0 = blockIdx.y * 128, n0 = blockIdx.x * 128;
    int tid = threadIdx.x;
    int tm = (tid >> 4) * 8, tn = (tid & 15) * 8;

    float acc[8][8];
#pragma unroll
    for (int i = 0; i < 8; i++)
#pragma unroll
        for (int j = 0; j < 8; j++) acc[i][j] = 0.f;

    int ar = tid >> 1, ac = (tid & 1) * 4;

    for (int k0 = 0; k0 < K; k0 += 8) {
        float4 av = *(const float4*)(Ab + (long)(m0 + ar) * lda + k0 + ac);
        As[ac + 0][ar] = av.x; As[ac + 1][ar] = av.y;
        As[ac + 2][ar] = av.z; As[ac + 3][ar] = av.w;
        if (!TB) {
            int br = tid >> 5, bc = (tid & 31) * 4;
            float4 bv = *(const float4*)(Bb + (long)(k0 + br) * ldb + n0 + bc);
            *(float4*)&Bs[br][bc] = bv;
        } else {
            int br = tid >> 1, bc = (tid & 1) * 4;
            float4 bv = *(const float4*)(Bb + (long)(n0 + br) * ldb + k0 + bc);
            Bs[bc + 0][br] = bv.x; Bs[bc + 1][br] = bv.y;
            Bs[bc + 2][br] = bv.z; Bs[bc + 3][br] = bv.w;
        }
        __syncthreads();
#pragma unroll
        for (int k = 0; k < 8; k++) {
            float a[8], b[8];
            *(float4*)(a)     = *(const float4*)&As[k][tm];
            *(float4*)(a + 4) = *(const float4*)&As[k][tm + 4];
            *(float4*)(b)     = *(const float4*)&Bs[k][tn];
            *(float4*)(b + 4) = *(const float4*)&Bs[k][tn + 4];
#pragma unroll
            for (int i = 0; i < 8; i++)
#pragma unroll
                for (int j = 0; j < 8; j++) acc[i][j] = fmaf(a[i], b[j], acc[i][j]);
        }
        __syncthreads();
    }
#pragma unroll
    for (int i = 0; i < 8; i++) {
        int m = m0 + tm + i;
#pragma unroll
        for (int j = 0; j < 8; j++) {
            int n = n0 + tn + j;
            float v = acc[i][j] * scale;
            if (bias) v += bias[n];
            if (RELU) v = fmaxf(v, 0.f);
            long idx;
            if (OM == 0)      idx = (long)bz * sC + (long)m * ldc + n;
            else if (OM == 1) idx = ((long)(n >> 8) * NTOK + m) * DH + (n & 255);
            else              idx = (long)m * DMOD + (long)bz * DH + n;
            C[idx] = v;
        }
    }
}

// ---------------- softmax over rows of length 1024 ----------------
__global__ void softmax_k(float* __restrict__ att) {
    long r = blockIdx.x;
    float* row = att + r * 1024;
    int tid = threadIdx.x;
    float v[4];
    float mx = -1e30f;
#pragma unroll
    for (int i = 0; i < 4; i++) { v[i] = row[tid + i * 256]; mx = fmaxf(mx, v[i]); }
    float bm = blockMax(mx);
    __shared__ float sb;
    if (tid == 0) sb = bm;
    __syncthreads();
    mx = sb;
    float s = 0.f;
#pragma unroll
    for (int i = 0; i < 4; i++) { v[i] = expf(v[i] - mx); s += v[i]; }
    float bs = blockSum(s);
    __shared__ float sv;
    if (tid == 0) sv = 1.f / bs;
    __syncthreads();
    float inv = sv;
#pragma unroll
    for (int i = 0; i < 4; i++) row[tid + i * 256] = v[i] * inv;
}

// ---------------- residual add + LayerNorm (rows of 2048) ----------------
__global__ void addln_k(const float* __restrict__ a, const float* __restrict__ b,
                        const float* __restrict__ g, const float* __restrict__ be,
                        float* __restrict__ o) {
    int n = blockIdx.x, tid = threadIdx.x;
    const float* pa = a + (size_t)n * DMOD;
    const float* pb = b + (size_t)n * DMOD;
    float x[8];
    float s = 0.f;
#pragma unroll
    for (int i = 0; i < 8; i++) {
        int d = tid + i * 256;
        x[i] = pa[d] + pb[d];
        s += x[i];
    }
    float ts = blockSum(s);
    __shared__ float mu, inv;
    if (tid == 0) mu = ts * (1.f / DMOD);
    __syncthreads();
    float m = mu, vs = 0.f;
#pragma unroll
    for (int i = 0; i < 8; i++) { float dv = x[i] - m; vs += dv * dv; }
    float tv = blockSum(vs);
    if (tid == 0) inv = rsqrtf(tv * (1.f / DMOD) + 1e-5f);
    __syncthreads();
    float iv = inv;
    float* po = o + (size_t)n * DMOD;
#pragma unroll
    for (int i = 0; i < 8; i++) {
        int d = tid + i * 256;
        po[d] = (x[i] - m) * iv * g[d] + be[d];
    }
}

// ---------------- batchnorm (batch stats over N) + relu, per column ----------------
__global__ void bn_k(const float* __restrict__ h, const float* __restrict__ g,
                     const float* __restrict__ b, float* __restrict__ o) {
    int j = blockIdx.x, tid = threadIdx.x;
    float s = 0.f;
    for (int r = tid; r < NTOK; r += 256) s += h[(size_t)r * DECH + j];
    float ts = blockSum(s);
    __shared__ float mu, inv;
    if (tid == 0) mu = ts * (1.f / NTOK);
    __syncthreads();
    float m = mu, vs = 0.f;
    for (int r = tid; r < NTOK; r += 256) { float d = h[(size_t)r * DECH + j] - m; vs += d * d; }
    float tv = blockSum(vs);
    if (tid == 0) inv = rsqrtf(tv * (1.f / NTOK) + 1e-5f);
    __syncthreads();
    float iv = inv, gg = g[j], bb = b[j];
    for (int r = tid; r < NTOK; r += 256) {
        float v = (h[(size_t)r * DECH + j] - m) * iv * gg + bb;
        o[(size_t)r * DECH + j] = fmaxf(v, 0.f);
    }
}

// ---------------- final small GEMM: [1024,1024] @ [1024,35] ----------------
__global__ void dec2_k(const float* __restrict__ hbn, const float* __restrict__ w,
                       const float* __restrict__ b, float* __restrict__ dist) {
    int idx = blockIdx.x * blockDim.x + threadIdx.x;
    if (idx >= NTOK * NCLS1) return;
    int n = idx / NCLS1, c = idx % NCLS1;
    const float* hr = hbn + (size_t)n * DECH;
    float s = 0.f;
    for (int j = 0; j < DECH; j++) s = fmaf(hr[j], w[(size_t)j * NCLS1 + c], s);
    dist[idx] = s + b[c];
}

// ---------------- orchestration ----------------
extern "C" void kernel_launch(void* const* d_in, const int* in_sizes, int n_in,
                              void* d_out, int out_size) {
    const float* feat = (const float*)d_in[0];
    const int*   fid  = (const int*)d_in[1];
    const int*   mn   = (const int*)d_in[2];
    const float* t_aw = (const float*)d_in[3];
    const float* t_ab = (const float*)d_in[4];
    const float* t_lg = (const float*)d_in[5];
    const float* t_lb = (const float*)d_in[6];
    const float* t_w1 = (const float*)d_in[7];
    const float* t_b1 = (const float*)d_in[8];
    const float* t_w2 = (const float*)d_in[9];
    const float* t_b2 = (const float*)d_in[10];
    const float* s_aw = (const float*)d_in[11];
    const float* s_ab = (const float*)d_in[12];
    const float* s_lg = (const float*)d_in[13];
    const float* s_lb = (const float*)d_in[14];
    const float* s_w1 = (const float*)d_in[15];
    const float* s_b1 = (const float*)d_in[16];
    const float* s_w2 = (const float*)d_in[17];
    const float* s_b2 = (const float*)d_in[18];
    const float* dw1  = (const float*)d_in[19];
    const float* db1  = (const float*)d_in[20];
    const float* bng  = (const float*)d_in[21];
    const float* bnb  = (const float*)d_in[22];
    const float* dw2  = (const float*)d_in[23];
    const float* db2  = (const float*)d_in[24];
    float* out = (float*)d_out;

    float* S = nullptr;
    cudaGetSymbolAddress((void**)&S, g_scratch);
    float* sfeat = S + OFF_SFEAT;
    float* qh  = S + OFF_QH;
    float* kh  = S + OFF_KH;
    float* vh  = S + OFF_VH;
    float* ob  = S + OFF_O;
    float* pb  = S + OFF_P;
    float* xb  = S + OFF_X;
    float* fb  = S + OFF_F;
    float* f2b = S + OFF_F2;
    float* c1  = S + OFF_C1;
    float* c2  = S + OFF_C2;
    float* att = S + OFF_ATT;
    float* hd  = S + OFF_HD;
    float* hbn = S + OFF_HBN;

    const size_t DD = (size_t)DMOD * DMOD;

    // 1) selector -> s_feat
    selector_k<<<NTOK, 256>>>(feat, fid, mn, sfeat);

    // 2) encoders
    auto run_enc = [&](const float* x0, const float* kvfix, bool selfattn,
                       const float* aw, const float* ab, const float* lg, const float* lb,
                       const float* w1, const float* b1, const float* w2, const float* b2,
                       float* result) {
        const float* cur = x0;
        for (int l = 0; l < NLAY; l++) {
            const float* kv = selfattn ? cur : kvfix;
            const float* W  = aw + (size_t)l * 4 * DD;
            const float* Bb = ab + (size_t)l * 4 * DMOD;
            // Q, K, V projections -> head-major [H][N][dh]
            gemm_k<false, 1, false><<<dim3(16, 8, 1), 256>>>(cur, W, Bb, qh,
                NTOK, DMOD, DMOD, DMOD, DMOD, 0, 0, 0, 0, 1.f);
            gemm_k<false, 1, false><<<dim3(16, 8, 1), 256>>>(kv, W + DD, Bb + DMOD, kh,
                NTOK, DMOD, DMOD, DMOD, DMOD, 0, 0, 0, 0, 1.f);
            gemm_k<false, 1, false><<<dim3(16, 8, 1), 256>>>(kv, W + 2 * DD, Bb + 2 * DMOD, vh,
                NTOK, DMOD, DMOD, DMOD, DMOD, 0, 0, 0, 0, 1.f);
            // S = Q Kt / sqrt(dh), batched over heads
            gemm_k<true, 0, false><<<dim3(8, 8, NHEAD), 256>>>(qh, kh, nullptr, att,
                NTOK, DH, NTOK, DH, DH, NTOK,
                (long)NTOK * DH, (long)NTOK * DH, (long)NTOK * NTOK, 0.0625f);
            softmax_k<<<NHEAD * NTOK, 256>>>(att);
            // O = att @ V, scatter back to [N, D]
            gemm_k<false, 2, false><<<dim3(2, 8, NHEAD), 256>>>(att, vh, nullptr, ob,
                NTOK, NTOK, DH, NTOK, DH, 0,
                (long)NTOK * NTOK, (long)NTOK * DH, 0, 1.f);
            // output projection
            gemm_k<false, 0, false><<<dim3(16, 8, 1), 256>>>(ob, W + 3 * DD, Bb + 3 * DMOD, pb,
                NTOK, DMOD, DMOD, DMOD, DMOD, DMOD, 0, 0, 0, 1.f);
            addln_k<<<NTOK, 256>>>(cur, pb, lg + (size_t)l * 2 * DMOD, lb + (size_t)l * 2 * DMOD, xb);
            // FFN
            gemm_k<false, 0, true><<<dim3(16, 8, 1), 256>>>(xb, w1 + (size_t)l * DMOD * DFFN,
                b1 + (size_t)l * DFFN, fb,
                NTOK, DMOD, DFFN, DMOD, DFFN, DFFN, 0, 0, 0, 1.f);
            gemm_k<false, 0, false><<<dim3(16, 8, 1), 256>>>(fb, w2 + (size_t)l * DFFN * DMOD,
                b2 + (size_t)l * DMOD, f2b,
                NTOK, DFFN, DMOD, DFFN, DMOD, DMOD, 0, 0, 0, 1.f);
            addln_k<<<NTOK, 256>>>(xb, f2b, lg + ((size_t)l * 2 + 1) * DMOD,
                                   lb + ((size_t)l * 2 + 1) * DMOD, result);
            cur = result;
        }
    };

    run_enc(feat, sfeat, false, t_aw, t_ab, t_lg, t_lb, t_w1, t_b1, t_w2, t_b2, c1);
    run_enc(c1, nullptr, true,  s_aw, s_ab, s_lg, s_lb, s_w1, s_b1, s_w2, s_b2, c2);

    // 3) decoder
    gemm_k<false, 0, false><<<dim3(8, 8, 1), 256>>>(c2, dw1, db1, hd,
        NTOK, DMOD, DECH, DMOD, DECH, DECH, 0, 0, 0, 1.f);
    bn_k<<<DECH, 256>>>(hd, bng, bnb, hbn);
    dec2_k<<<(NTOK * NCLS1 + 255) / 256, 256>>>(hbn, dw2, db2, out + (size_t)NTOK * DMOD);

    // 4) first output: x (spatial encoder output)
    cudaMemcpyAsync(out, c2, (size_t)NTOK * DMOD * sizeof(float),
                    cudaMemcpyDeviceToDevice);
}

// round 2
// speedup vs baseline: 1.1288x; 1.1288x over previous
#include <cuda_runtime.h>
#include <math.h>
#include <stdint.h>

// ---------------- problem constants ----------------
#define NTOK 1024
#define DMOD 2048
#define NHEAD 8
#define DH 256
#define NLAY 3
#define MM 16
#define KSEL 8
#define DFFN 2048
#define DECH 1024
#define NCLS1 35

// ---------------- scratch (static device memory; no allocs) ----------------
static constexpr size_t ND_ = (size_t)NTOK * DMOD;
static constexpr size_t OFF_SFEAT = 0;
static constexpr size_t OFF_QH    = 1 * ND_;
static constexpr size_t OFF_KH    = 2 * ND_;
static constexpr size_t OFF_VH    = 3 * ND_;
static constexpr size_t OFF_O     = 4 * ND_;
static constexpr size_t OFF_P     = 5 * ND_;
static constexpr size_t OFF_X     = 6 * ND_;
static constexpr size_t OFF_F     = 7 * ND_;
static constexpr size_t OFF_F2    = 8 * ND_;
static constexpr size_t OFF_C1    = 9 * ND_;
static constexpr size_t OFF_C2    = 10 * ND_;
static constexpr size_t OFF_ATT   = 11 * ND_;
static constexpr size_t OFF_HD    = OFF_ATT + (size_t)NHEAD * NTOK * NTOK;
static constexpr size_t OFF_HBN   = OFF_HD + (size_t)NTOK * DECH;
static constexpr size_t SCR_FLOATS = OFF_HBN + (size_t)NTOK * DECH;

__device__ float g_scratch[SCR_FLOATS];

// ---------------- reductions ----------------
__device__ __forceinline__ float warpSum(float v) {
#pragma unroll
    for (int o = 16; o; o >>= 1) v += __shfl_down_sync(0xffffffffu, v, o);
    return v;
}
__device__ __forceinline__ float warpMax(float v) {
#pragma unroll
    for (int o = 16; o; o >>= 1) v = fmaxf(v, __shfl_down_sync(0xffffffffu, v, o));
    return v;
}
__device__ float blockSum(float v) {
    __shared__ float s[8];
    int lane = threadIdx.x & 31, w = threadIdx.x >> 5;
    v = warpSum(v);
    if (lane == 0) s[w] = v;
    __syncthreads();
    float r = 0.f;
    if (w == 0) { r = (lane < 8) ? s[lane] : 0.f; r = warpSum(r); }
    __syncthreads();
    return r;
}
__device__ float blockMax(float v) {
    __shared__ float s[8];
    int lane = threadIdx.x & 31, w = threadIdx.x >> 5;
    v = warpMax(v);
    if (lane == 0) s[w] = v;
    __syncthreads();
    float r = -1e30f;
    if (w == 0) { r = (lane < 8) ? s[lane] : -1e30f; r = warpMax(r); }
    __syncthreads();
    return r;
}

#define PECOEF (-0.008994473019508232f)   /* -ln(10000)/1024 */

// ---------------- selector ----------------
__global__ void selector_k(const float* __restrict__ feat, const int* __restrict__ fid,
                           const int* __restrict__ mn, float* __restrict__ sf) {
    int n = blockIdx.x, tid = threadIdx.x;
    __shared__ int nodes[MM];
    __shared__ int pos[MM];
    __shared__ float sc[MM];
    __shared__ int sel[KSEL];
    __shared__ float wgt[KSEL];

    if (tid < MM) nodes[tid] = mn[n * MM + tid];
    __syncthreads();
    if (tid == 0) {
        int p = 0, prev = fid[nodes[0]];
        pos[0] = 0;
        for (int m = 1; m < MM; m++) {
            int f = fid[nodes[m]];
            if (f != prev) { p++; prev = f; }
            pos[m] = p;
        }
    }
    __syncthreads();

    const float* fn = feat + (size_t)n * DMOD;
    float part[MM];
#pragma unroll
    for (int m = 0; m < MM; m++) part[m] = 0.f;
    for (int d = tid; d < DMOD; d += 256) {
        float fv = fn[d];
        int i = d >> 1;
        float fr = expf((float)i * PECOEF);
        bool odd = d & 1;
#pragma unroll
        for (int m = 0; m < MM; m++) {
            float ang = (float)pos[m] * fr;
            float pev = odd ? cosf(ang) : sinf(ang);
            part[m] += fv * (feat[(size_t)nodes[m] * DMOD + d] + pev);
        }
    }
    const float scale = 0.022097086912079608f; // 1/sqrt(2048)
    for (int m = 0; m < MM; m++) {
        float ts = blockSum(part[m]);
        if (tid == 0) sc[m] = ts * scale;
    }
    __syncthreads();

    if (tid == 0) {
        unsigned used = 0;
        float tv[KSEL];
        for (int k = 0; k < KSEL; k++) {
            float best = -1e30f; int bi = 0;
            for (int m = 0; m < MM; m++)
                if (!((used >> m) & 1) && sc[m] > best) { best = sc[m]; bi = m; }
            used |= 1u << bi; sel[k] = bi; tv[k] = best;
        }
        float mx = tv[0], ssum = 0.f;
        for (int k = 0; k < KSEL; k++) { wgt[k] = expf(tv[k] - mx); ssum += wgt[k]; }
        float inv = 1.f / ssum;
        for (int k = 0; k < KSEL; k++) wgt[k] *= inv;
    }
    __syncthreads();

    float* po = sf + (size_t)n * DMOD;
    for (int d = tid; d < DMOD; d += 256) {
        int i = d >> 1;
        float fr = expf((float)i * PECOEF);
        bool odd = d & 1;
        float acc = 0.f;
#pragma unroll
        for (int k = 0; k < KSEL; k++) {
            int m = sel[k];
            float ang = (float)pos[m] * fr;
            float pev = odd ? cosf(ang) : sinf(ang);
            acc += wgt[k] * (feat[(size_t)nodes[m] * DMOD + d] + pev);
        }
        po[d] = acc;
    }
}

// ---------------- tensor-core GEMM: 3xTF32, 128x128 tile, mma.m16n8k8 ----------------
__device__ __forceinline__ uint32_t f2tf(float x) {
    uint32_t r;
    asm("cvt.rna.tf32.f32 %0, %1;" : "=r"(r) : "f"(x));
    return r;
}

#define MMA_TF32(c, a, b)                                                      \
    asm volatile(                                                              \
        "mma.sync.aligned.m16n8k8.row.col.f32.tf32.tf32.f32 "                 \
        "{%0,%1,%2,%3},{%4,%5,%6,%7},{%8,%9},{%0,%1,%2,%3};\n"                \
        : "+f"(c[0]), "+f"(c[1]), "+f"(c[2]), "+f"(c[3])                       \
        : "r"(a[0]), "r"(a[1]), "r"(a[2]), "r"(a[3]), "r"(b[0]), "r"(b[1]))

// OM=0: C[bz*sC + m*ldc + n]
// OM=1: split-head scatter  C[((n>>8)*NTOK + m)*DH + (n&255)]
// OM=2: merge-head scatter  C[m*DMOD + bz*DH + n]
template <bool TB, int OM, bool RELU>
__global__ void __launch_bounds__(256)
tgemm_k(const float* __restrict__ A, const float* __restrict__ B,
        const float* __restrict__ bias, float* __restrict__ C,
        int K, int lda, int ldb, int ldc,
        long sA, long sB, long sC, float scale) {
    __shared__ float As[128][36];   // [m][k], lead 36 -> conflict-free frag loads
    __shared__ float Bs[32][136];   // [k][n], lead 136 -> conflict-free frag loads
    int bz = blockIdx.z;
    const float* Ab = A + (long)bz * sA;
    const float* Bb = B + (long)bz * sB;
    int m0 = blockIdx.y * 128, n0 = blockIdx.x * 128;
    int tid = threadIdx.x;
    int warpId = tid >> 5, lane = tid & 31;
    int g = lane >> 2, tig = lane & 3;
    int wm = warpId & 1, wn = warpId >> 1;      // 2 x 4 warps
    int mBase = wm * 64, nBase = wn * 32;       // warp tile 64 x 32

    float acc[4][4][4];
#pragma unroll
    for (int i = 0; i < 4; i++)
#pragma unroll
        for (int j = 0; j < 4; j++)
#pragma unroll
            for (int r = 0; r < 4; r++) acc[i][j][r] = 0.f;

    int ar = tid >> 1, ac = (tid & 1) * 16;
    int bk = tid >> 3, bn = (tid & 7) * 16;

    for (int k0 = 0; k0 < K; k0 += 32) {
        const float* ap = Ab + (long)(m0 + ar) * lda + k0 + ac;
#pragma unroll
        for (int i = 0; i < 4; i++)
            *(float4*)&As[ar][ac + 4 * i] = *(const float4*)(ap + 4 * i);
        if (!TB) {
            const float* bp = Bb + (long)(k0 + bk) * ldb + n0 + bn;
#pragma unroll
            for (int i = 0; i < 4; i++)
                *(float4*)&Bs[bk][bn + 4 * i] = *(const float4*)(bp + 4 * i);
        } else {
            const float* bp = Bb + (long)(n0 + ar) * ldb + k0 + ac;
#pragma unroll
            for (int i = 0; i < 4; i++) {
                float4 v = *(const float4*)(bp + 4 * i);
                Bs[ac + 4 * i + 0][ar] = v.x;
                Bs[ac + 4 * i + 1][ar] = v.y;
                Bs[ac + 4 * i + 2][ar] = v.z;
                Bs[ac + 4 * i + 3][ar] = v.w;
            }
        }
        __syncthreads();
#pragma unroll
        for (int ks = 0; ks < 4; ks++) {
            int kk = ks * 8;
            uint32_t ah[4][4], al[4][4], bh[4][2], bl[4][2];
#pragma unroll
            for (int mi = 0; mi < 4; mi++) {
                int r0 = mBase + mi * 16 + g;
                float v0 = As[r0][kk + tig];
                float v1 = As[r0 + 8][kk + tig];
                float v2 = As[r0][kk + tig + 4];
                float v3 = As[r0 + 8][kk + tig + 4];
                ah[mi][0] = f2tf(v0); al[mi][0] = __float_as_uint(v0 - __uint_as_float(ah[mi][0]));
                ah[mi][1] = f2tf(v1); al[mi][1] = __float_as_uint(v1 - __uint_as_float(ah[mi][1]));
                ah[mi][2] = f2tf(v2); al[mi][2] = __float_as_uint(v2 - __uint_as_float(ah[mi][2]));
                ah[mi][3] = f2tf(v3); al[mi][3] = __float_as_uint(v3 - __uint_as_float(ah[mi][3]));
            }
#pragma unroll
            for (int ni = 0; ni < 4; ni++) {
                int c0 = nBase + ni * 8 + g;
                float w0 = Bs[kk + tig][c0];
                float w1 = Bs[kk + tig + 4][c0];
                bh[ni][0] = f2tf(w0); bl[ni][0] = __float_as_uint(w0 - __uint_as_float(bh[ni][0]));
                bh[ni][1] = f2tf(w1); bl[ni][1] = __float_as_uint(w1 - __uint_as_float(bh[ni][1]));
            }
#pragma unroll
            for (int mi = 0; mi < 4; mi++)
#pragma unroll
                for (int ni = 0; ni < 4; ni++) {
                    MMA_TF32(acc[mi][ni], ah[mi], bh[ni]);
                    MMA_TF32(acc[mi][ni], ah[mi], bl[ni]);
                    MMA_TF32(acc[mi][ni], al[mi], bh[ni]);
                }
        }
        __syncthreads();
    }

#pragma unroll
    for (int mi = 0; mi < 4; mi++) {
#pragma unroll
        for (int ni = 0; ni < 4; ni++) {
            int row0 = m0 + mBase + mi * 16 + g;
            int col0 = n0 + nBase + ni * 8 + tig * 2;
#pragma unroll
            for (int h = 0; h < 2; h++) {
                int row = row0 + 8 * h;
                float vx = acc[mi][ni][2 * h + 0] * scale;
                float vy = acc[mi][ni][2 * h + 1] * scale;
                if (bias) { vx += bias[col0]; vy += bias[col0 + 1]; }
                if (RELU) { vx = fmaxf(vx, 0.f); vy = fmaxf(vy, 0.f); }
                long idx;
                if (OM == 0)      idx = (long)bz * sC + (long)row * ldc + col0;
                else if (OM == 1) idx = ((long)(col0 >> 8) * NTOK + row) * DH + (col0 & 255);
                else              idx = (long)row * DMOD + (long)bz * DH + col0;
                C[idx] = vx;
                C[idx + 1] = vy;
            }
        }
    }
}

// ---------------- softmax over rows of length 1024 ----------------
__global__ void softmax_k(float* __restrict__ att) {
    long r = blockIdx.x;
    float* row = att + r * 1024;
    int tid = threadIdx.x;
    float v[4];
    float mx = -1e30f;
#pragma unroll
    for (int i = 0; i < 4; i++) { v[i] = row[tid + i * 256]; mx = fmaxf(mx, v[i]); }
    float bm = blockMax(mx);
    __shared__ float sb;
    if (tid == 0) sb = bm;
    __syncthreads();
    mx = sb;
    float s = 0.f;
#pragma unroll
    for (int i = 0; i < 4; i++) { v[i] = expf(v[i] - mx); s += v[i]; }
    float bs = blockSum(s);
    __shared__ float sv;
    if (tid == 0) sv = 1.f / bs;
    __syncthreads();
    float inv = sv;
#pragma unroll
    for (int i = 0; i < 4; i++) row[tid + i * 256] = v[i] * inv;
}

// ---------------- residual add + LayerNorm (rows of 2048) ----------------
__global__ void addln_k(const float* __restrict__ a, const float* __restrict__ b,
                        const float* __restrict__ g, const float* __restrict__ be,
                        float* __restrict__ o) {
    int n = blockIdx.x, tid = threadIdx.x;
    const float* pa = a + (size_t)n * DMOD;
    const float* pb = b + (size_t)n * DMOD;
    float x[8];
    float s = 0.f;
#pragma unroll
    for (int i = 0; i < 8; i++) {
        int d = tid + i * 256;
        x[i] = pa[d] + pb[d];
        s += x[i];
    }
    float ts = blockSum(s);
    __shared__ float mu, inv;
    if (tid == 0) mu = ts * (1.f / DMOD);
    __syncthreads();
    float m = mu, vs = 0.f;
#pragma unroll
    for (int i = 0; i < 8; i++) { float dv = x[i] - m; vs += dv * dv; }
    float tv = blockSum(vs);
    if (tid == 0) inv = rsqrtf(tv * (1.f / DMOD) + 1e-5f);
    __syncthreads();
    float iv = inv;
    float* po = o + (size_t)n * DMOD;
#pragma unroll
    for (int i = 0; i < 8; i++) {
        int d = tid + i * 256;
        po[d] = (x[i] - m) * iv * g[d] + be[d];
    }
}

// ---------------- batchnorm (batch stats over N) + relu, per column ----------------
__global__ void bn_k(const float* __restrict__ h, const float* __restrict__ g,
                     const float* __restrict__ b, float* __restrict__ o) {
    int j = blockIdx.x, tid = threadIdx.x;
    float s = 0.f;
    for (int r = tid; r < NTOK; r += 256) s += h[(size_t)r * DECH + j];
    float ts = blockSum(s);
    __shared__ float mu, inv;
    if (tid == 0) mu = ts * (1.f / NTOK);
    __syncthreads();
    float m = mu, vs = 0.f;
    for (int r = tid; r < NTOK; r += 256) { float d = h[(size_t)r * DECH + j] - m; vs += d * d; }
    float tv = blockSum(vs);
    if (tid == 0) inv = rsqrtf(tv * (1.f / NTOK) + 1e-5f);
    __syncthreads();
    float iv = inv, gg = g[j], bb = b[j];
    for (int r = tid; r < NTOK; r += 256) {
        float v = (h[(size_t)r * DECH + j] - m) * iv * gg + bb;
        o[(size_t)r * DECH + j] = fmaxf(v, 0.f);
    }
}

// ---------------- final small GEMM: [1024,1024] @ [1024,35] ----------------
__global__ void dec2_k(const float* __restrict__ hbn, const float* __restrict__ w,
                       const float* __restrict__ b, float* __restrict__ dist) {
    int idx = blockIdx.x * blockDim.x + threadIdx.x;
    if (idx >= NTOK * NCLS1) return;
    int n = idx / NCLS1, c = idx % NCLS1;
    const float* hr = hbn + (size_t)n * DECH;
    float s = 0.f;
    for (int j = 0; j < DECH; j++) s = fmaf(hr[j], w[(size_t)j * NCLS1 + c], s);
    dist[idx] = s + b[c];
}

// ---------------- orchestration ----------------
extern "C" void kernel_launch(void* const* d_in, const int* in_sizes, int n_in,
                              void* d_out, int out_size) {
    const float* feat = (const float*)d_in[0];
    const int*   fid  = (const int*)d_in[1];
    const int*   mn   = (const int*)d_in[2];
    const float* t_aw = (const float*)d_in[3];
    const float* t_ab = (const float*)d_in[4];
    const float* t_lg = (const float*)d_in[5];
    const float* t_lb = (const float*)d_in[6];
    const float* t_w1 = (const float*)d_in[7];
    const float* t_b1 = (const float*)d_in[8];
    const float* t_w2 = (const float*)d_in[9];
    const float* t_b2 = (const float*)d_in[10];
    const float* s_aw = (const float*)d_in[11];
    const float* s_ab = (const float*)d_in[12];
    const float* s_lg = (const float*)d_in[13];
    const float* s_lb = (const float*)d_in[14];
    const float* s_w1 = (const float*)d_in[15];
    const float* s_b1 = (const float*)d_in[16];
    const float* s_w2 = (const float*)d_in[17];
    const float* s_b2 = (const float*)d_in[18];
    const float* dw1  = (const float*)d_in[19];
    const float* db1  = (const float*)d_in[20];
    const float* bng  = (const float*)d_in[21];
    const float* bnb  = (const float*)d_in[22];
    const float* dw2  = (const float*)d_in[23];
    const float* db2  = (const float*)d_in[24];
    float* out = (float*)d_out;

    float* S = nullptr;
    cudaGetSymbolAddress((void**)&S, g_scratch);
    float* sfeat = S + OFF_SFEAT;
    float* qh  = S + OFF_QH;
    float* kh  = S + OFF_KH;
    float* vh  = S + OFF_VH;
    float* ob  = S + OFF_O;
    float* pb  = S + OFF_P;
    float* xb  = S + OFF_X;
    float* fb  = S + OFF_F;
    float* f2b = S + OFF_F2;
    float* c1  = S + OFF_C1;
    float* c2  = S + OFF_C2;
    float* att = S + OFF_ATT;
    float* hd  = S + OFF_HD;
    float* hbn = S + OFF_HBN;

    const size_t DD = (size_t)DMOD * DMOD;

    // 1) selector -> s_feat
    selector_k<<<NTOK, 256>>>(feat, fid, mn, sfeat);

    // 2) encoders
    auto run_enc = [&](const float* x0, const float* kvfix, bool selfattn,
                       const float* aw, const float* ab, const float* lg, const float* lb,
                       const float* w1, const float* b1, const float* w2, const float* b2,
                       float* result) {
        const float* cur = x0;
        for (int l = 0; l < NLAY; l++) {
            const float* kv = selfattn ? cur : kvfix;
            const float* W  = aw + (size_t)l * 4 * DD;
            const float* Bb = ab + (size_t)l * 4 * DMOD;
            // Q, K, V projections -> head-major [H][N][dh]
            tgemm_k<false, 1, false><<<dim3(16, 8, 1), 256>>>(cur, W, Bb, qh,
                DMOD, DMOD, DMOD, 0, 0, 0, 0, 1.f);
            tgemm_k<false, 1, false><<<dim3(16, 8, 1), 256>>>(kv, W + DD, Bb + DMOD, kh,
                DMOD, DMOD, DMOD, 0, 0, 0, 0, 1.f);
            tgemm_k<false, 1, false><<<dim3(16, 8, 1), 256>>>(kv, W + 2 * DD, Bb + 2 * DMOD, vh,
                DMOD, DMOD, DMOD, 0, 0, 0, 0, 1.f);
            // S = Q Kt / sqrt(dh), batched over heads
            tgemm_k<true, 0, false><<<dim3(8, 8, NHEAD), 256>>>(qh, kh, nullptr, att,
                DH, DH, DH, NTOK,
                (long)NTOK * DH, (long)NTOK * DH, (long)NTOK * NTOK, 0.0625f);
            softmax_k<<<NHEAD * NTOK, 256>>>(att);
            // O = att @ V, scatter back to [N, D]
            tgemm_k<false, 2, false><<<dim3(2, 8, NHEAD), 256>>>(att, vh, nullptr, ob,
                NTOK, NTOK, DH, 0,
                (long)NTOK * NTOK, (long)NTOK * DH, 0, 1.f);
            // output projection
            tgemm_k<false, 0, false><<<dim3(16, 8, 1), 256>>>(ob, W + 3 * DD, Bb + 3 * DMOD, pb,
                DMOD, DMOD, DMOD, DMOD, 0, 0, 0, 1.f);
            addln_k<<<NTOK, 256>>>(cur, pb, lg + (size_t)l * 2 * DMOD, lb + (size_t)l * 2 * DMOD, xb);
            // FFN
            tgemm_k<false, 0, true><<<dim3(16, 8, 1), 256>>>(xb, w1 + (size_t)l * DMOD * DFFN,
                b1 + (size_t)l * DFFN, fb,
                DMOD, DMOD, DFFN, DFFN, 0, 0, 0, 1.f);
            tgemm_k<false, 0, false><<<dim3(16, 8, 1), 256>>>(fb, w2 + (size_t)l * DFFN * DMOD,
                b2 + (size_t)l * DMOD, f2b,
                DFFN, DFFN, DMOD, DMOD, 0, 0, 0, 1.f);
            addln_k<<<NTOK, 256>>>(xb, f2b, lg + ((size_t)l * 2 + 1) * DMOD,
                                   lb + ((size_t)l * 2 + 1) * DMOD, result);
            cur = result;
        }
    };

    run_enc(feat, sfeat, false, t_aw, t_ab, t_lg, t_lb, t_w1, t_b1, t_w2, t_b2, c1);
    run_enc(c1, nullptr, true,  s_aw, s_ab, s_lg, s_lb, s_w1, s_b1, s_w2, s_b2, c2);

    // 3) decoder
    tgemm_k<false, 0, false><<<dim3(8, 8, 1), 256>>>(c2, dw1, db1, hd,
        DMOD, DMOD, DECH, DECH, 0, 0, 0, 1.f);
    bn_k<<<DECH, 256>>>(hd, bng, bnb, hbn);
    dec2_k<<<(NTOK * NCLS1 + 255) / 256, 256>>>(hbn, dw2, db2, out + (size_t)NTOK * DMOD);

    // 4) first output: x (spatial encoder output)
    cudaMemcpyAsync(out, c2, (size_t)NTOK * DMOD * sizeof(float),
                    cudaMemcpyDeviceToDevice);
}

// round 3
// speedup vs baseline: 1.7070x; 1.5122x over previous
#include <cuda_runtime.h>
#include <math.h>
#include <stdint.h>

// ---------------- problem constants ----------------
#define NTOK 1024
#define DMOD 2048
#define NHEAD 8
#define DH 256
#define NLAY 3
#define MM 16
#define KSEL 8
#define DFFN 2048
#define DECH 1024
#define NCLS1 35

// ---------------- scratch (static device memory; no allocs) ----------------
static constexpr size_t ND_ = (size_t)NTOK * DMOD;
static constexpr size_t OFF_SFEAT = 0;
static constexpr size_t OFF_QH    = 1 * ND_;
static constexpr size_t OFF_KH    = 2 * ND_;
static constexpr size_t OFF_VH    = 3 * ND_;
static constexpr size_t OFF_O     = 4 * ND_;
static constexpr size_t OFF_P     = 5 * ND_;
static constexpr size_t OFF_X     = 6 * ND_;
static constexpr size_t OFF_F     = 7 * ND_;
static constexpr size_t OFF_F2    = 8 * ND_;
static constexpr size_t OFF_C1    = 9 * ND_;
static constexpr size_t OFF_C2    = 10 * ND_;
static constexpr size_t OFF_ATT   = 11 * ND_;
static constexpr size_t OFF_HD    = OFF_ATT + (size_t)NHEAD * NTOK * NTOK;
static constexpr size_t OFF_HBN   = OFF_HD + (size_t)NTOK * DECH;
static constexpr size_t SCR_FLOATS = OFF_HBN + (size_t)NTOK * DECH;

__device__ float g_scratch[SCR_FLOATS];

// ---------------- reductions ----------------
__device__ __forceinline__ float warpSum(float v) {
#pragma unroll
    for (int o = 16; o; o >>= 1) v += __shfl_down_sync(0xffffffffu, v, o);
    return v;
}
__device__ __forceinline__ float warpMax(float v) {
#pragma unroll
    for (int o = 16; o; o >>= 1) v = fmaxf(v, __shfl_down_sync(0xffffffffu, v, o));
    return v;
}
__device__ float blockSum(float v) {
    __shared__ float s[8];
    int lane = threadIdx.x & 31, w = threadIdx.x >> 5;
    v = warpSum(v);
    if (lane == 0) s[w] = v;
    __syncthreads();
    float r = 0.f;
    if (w == 0) { r = (lane < 8) ? s[lane] : 0.f; r = warpSum(r); }
    __syncthreads();
    return r;
}
__device__ float blockMax(float v) {
    __shared__ float s[8];
    int lane = threadIdx.x & 31, w = threadIdx.x >> 5;
    v = warpMax(v);
    if (lane == 0) s[w] = v;
    __syncthreads();
    float r = -1e30f;
    if (w == 0) { r = (lane < 8) ? s[lane] : -1e30f; r = warpMax(r); }
    __syncthreads();
    return r;
}

#define PECOEF (-0.008994473019508232f)   /* -ln(10000)/1024 */

// ---------------- selector ----------------
__global__ void selector_k(const float* __restrict__ feat, const int* __restrict__ fid,
                           const int* __restrict__ mn, float* __restrict__ sf) {
    int n = blockIdx.x, tid = threadIdx.x;
    __shared__ int nodes[MM];
    __shared__ int pos[MM];
    __shared__ float sc[MM];
    __shared__ int sel[KSEL];
    __shared__ float wgt[KSEL];

    if (tid < MM) nodes[tid] = mn[n * MM + tid];
    __syncthreads();
    if (tid == 0) {
        int p = 0, prev = fid[nodes[0]];
        pos[0] = 0;
        for (int m = 1; m < MM; m++) {
            int f = fid[nodes[m]];
            if (f != prev) { p++; prev = f; }
            pos[m] = p;
        }
    }
    __syncthreads();

    const float* fn = feat + (size_t)n * DMOD;
    float part[MM];
#pragma unroll
    for (int m = 0; m < MM; m++) part[m] = 0.f;
    for (int d = tid; d < DMOD; d += 256) {
        float fv = fn[d];
        int i = d >> 1;
        float fr = expf((float)i * PECOEF);
        bool odd = d & 1;
#pragma unroll
        for (int m = 0; m < MM; m++) {
            float ang = (float)pos[m] * fr;
            float pev = odd ? cosf(ang) : sinf(ang);
            part[m] += fv * (feat[(size_t)nodes[m] * DMOD + d] + pev);
        }
    }
    const float scale = 0.022097086912079608f; // 1/sqrt(2048)
    for (int m = 0; m < MM; m++) {
        float ts = blockSum(part[m]);
        if (tid == 0) sc[m] = ts * scale;
    }
    __syncthreads();

    if (tid == 0) {
        unsigned used = 0;
        float tv[KSEL];
        for (int k = 0; k < KSEL; k++) {
            float best = -1e30f; int bi = 0;
            for (int m = 0; m < MM; m++)
                if (!((used >> m) & 1) && sc[m] > best) { best = sc[m]; bi = m; }
            used |= 1u << bi; sel[k] = bi; tv[k] = best;
        }
        float mx = tv[0], ssum = 0.f;
        for (int k = 0; k < KSEL; k++) { wgt[k] = expf(tv[k] - mx); ssum += wgt[k]; }
        float inv = 1.f / ssum;
        for (int k = 0; k < KSEL; k++) wgt[k] *= inv;
    }
    __syncthreads();

    float* po = sf + (size_t)n * DMOD;
    for (int d = tid; d < DMOD; d += 256) {
        int i = d >> 1;
        float fr = expf((float)i * PECOEF);
        bool odd = d & 1;
        float acc = 0.f;
#pragma unroll
        for (int k = 0; k < KSEL; k++) {
            int m = sel[k];
            float ang = (float)pos[m] * fr;
            float pev = odd ? cosf(ang) : sinf(ang);
            acc += wgt[k] * (feat[(size_t)nodes[m] * DMOD + d] + pev);
        }
        po[d] = acc;
    }
}

// ---------------- tensor-core GEMM: 3xTF32, 128x128 tile, mma.m16n8k8 ----------------
__device__ __forceinline__ uint32_t f2tf(float x) {
    uint32_t r;
    asm("cvt.rna.tf32.f32 %0, %1;" : "=r"(r) : "f"(x));
    return r;
}

#define MMA_TF32(c, a, b)                                                      \
    asm volatile(                                                              \
        "mma.sync.aligned.m16n8k8.row.col.f32.tf32.tf32.f32 "                 \
        "{%0,%1,%2,%3},{%4,%5,%6,%7},{%8,%9},{%0,%1,%2,%3};\n"                \
        : "+f"(c[0]), "+f"(c[1]), "+f"(c[2]), "+f"(c[3])                       \
        : "r"(a[0]), "r"(a[1]), "r"(a[2]), "r"(a[3]), "r"(b[0]), "r"(b[1]))

// OM=0: C[bz*sC + m*ldc + n]
// OM=1: split-head scatter  C[((n>>8)*NTOK + m)*DH + (n&255)]
// OM=2: merge-head scatter  C[m*DMOD + bz*DH + n]
template <bool TB, int OM, bool RELU>
__global__ void __launch_bounds__(256)
tgemm_k(const float* __restrict__ A, const float* __restrict__ B,
        const float* __restrict__ bias, float* __restrict__ C,
        int K, int lda, int ldb, int ldc,
        long sA, long sB, long sC, float scale) {
    __shared__ float As[128][36];   // [m][k], lead 36 -> conflict-free frag loads
    __shared__ float Bs[32][136];   // [k][n], lead 136 -> conflict-free frag loads
    int bz = blockIdx.z;
    const float* Ab = A + (long)bz * sA;
    const float* Bb = B + (long)bz * sB;
    int m0 = blockIdx.y * 128, n0 = blockIdx.x * 128;
    int tid = threadIdx.x;
    int warpId = tid >> 5, lane = tid & 31;
    int g = lane >> 2, tig = lane & 3;
    int wm = warpId & 1, wn = warpId >> 1;      // 2 x 4 warps
    int mBase = wm * 64, nBase = wn * 32;       // warp tile 64 x 32

    float acc[4][4][4];
#pragma unroll
    for (int i = 0; i < 4; i++)
#pragma unroll
        for (int j = 0; j < 4; j++)
#pragma unroll
            for (int r = 0; r < 4; r++) acc[i][j][r] = 0.f;

    int ar = tid >> 1, ac = (tid & 1) * 16;
    int bk = tid >> 3, bn = (tid & 7) * 16;

    for (int k0 = 0; k0 < K; k0 += 32) {
        const float* ap = Ab + (long)(m0 + ar) * lda + k0 + ac;
#pragma unroll
        for (int i = 0; i < 4; i++)
            *(float4*)&As[ar][ac + 4 * i] = *(const float4*)(ap + 4 * i);
        if (!TB) {
            const float* bp = Bb + (long)(k0 + bk) * ldb + n0 + bn;
#pragma unroll
            for (int i = 0; i < 4; i++)
                *(float4*)&Bs[bk][bn + 4 * i] = *(const float4*)(bp + 4 * i);
        } else {
            const float* bp = Bb + (long)(n0 + ar) * ldb + k0 + ac;
#pragma unroll
            for (int i = 0; i < 4; i++) {
                float4 v = *(const float4*)(bp + 4 * i);
                Bs[ac + 4 * i + 0][ar] = v.x;
                Bs[ac + 4 * i + 1][ar] = v.y;
                Bs[ac + 4 * i + 2][ar] = v.z;
                Bs[ac + 4 * i + 3][ar] = v.w;
            }
        }
        __syncthreads();
#pragma unroll
        for (int ks = 0; ks < 4; ks++) {
            int kk = ks * 8;
            uint32_t ah[4][4], al[4][4], bh[4][2], bl[4][2];
#pragma unroll
            for (int mi = 0; mi < 4; mi++) {
                int r0 = mBase + mi * 16 + g;
                float v0 = As[r0][kk + tig];
                float v1 = As[r0 + 8][kk + tig];
                float v2 = As[r0][kk + tig + 4];
                float v3 = As[r0 + 8][kk + tig + 4];
                ah[mi][0] = f2tf(v0); al[mi][0] = __float_as_uint(v0 - __uint_as_float(ah[mi][0]));
                ah[mi][1] = f2tf(v1); al[mi][1] = __float_as_uint(v1 - __uint_as_float(ah[mi][1]));
                ah[mi][2] = f2tf(v2); al[mi][2] = __float_as_uint(v2 - __uint_as_float(ah[mi][2]));
                ah[mi][3] = f2tf(v3); al[mi][3] = __float_as_uint(v3 - __uint_as_float(ah[mi][3]));
            }
#pragma unroll
            for (int ni = 0; ni < 4; ni++) {
                int c0 = nBase + ni * 8 + g;
                float w0 = Bs[kk + tig][c0];
                float w1 = Bs[kk + tig + 4][c0];
                bh[ni][0] = f2tf(w0); bl[ni][0] = __float_as_uint(w0 - __uint_as_float(bh[ni][0]));
                bh[ni][1] = f2tf(w1); bl[ni][1] = __float_as_uint(w1 - __uint_as_float(bh[ni][1]));
            }
#pragma unroll
            for (int mi = 0; mi < 4; mi++)
#pragma unroll
                for (int ni = 0; ni < 4; ni++) {
                    MMA_TF32(acc[mi][ni], ah[mi], bh[ni]);
                    MMA_TF32(acc[mi][ni], ah[mi], bl[ni]);
                    MMA_TF32(acc[mi][ni], al[mi], bh[ni]);
                }
        }
        __syncthreads();
    }

#pragma unroll
    for (int mi = 0; mi < 4; mi++) {
#pragma unroll
        for (int ni = 0; ni < 4; ni++) {
            int row0 = m0 + mBase + mi * 16 + g;
            int col0 = n0 + nBase + ni * 8 + tig * 2;
#pragma unroll
            for (int h = 0; h < 2; h++) {
                int row = row0 + 8 * h;
                float vx = acc[mi][ni][2 * h + 0] * scale;
                float vy = acc[mi][ni][2 * h + 1] * scale;
                if (bias) { vx += bias[col0]; vy += bias[col0 + 1]; }
                if (RELU) { vx = fmaxf(vx, 0.f); vy = fmaxf(vy, 0.f); }
                long idx;
                if (OM == 0)      idx = (long)bz * sC + (long)row * ldc + col0;
                else if (OM == 1) idx = ((long)(col0 >> 8) * NTOK + row) * DH + (col0 & 255);
                else              idx = (long)row * DMOD + (long)bz * DH + col0;
                C[idx] = vx;
                C[idx + 1] = vy;
            }
        }
    }
}

// ---------------- softmax over rows of length 1024 ----------------
__global__ void softmax_k(float* __restrict__ att) {
    long r = blockIdx.x;
    float* row = att + r * 1024;
    int tid = threadIdx.x;
    float v[4];
    float mx = -1e30f;
#pragma unroll
    for (int i = 0; i < 4; i++) { v[i] = row[tid + i * 256]; mx = fmaxf(mx, v[i]); }
    float bm = blockMax(mx);
    __shared__ float sb;
    if (tid == 0) sb = bm;
    __syncthreads();
    mx = sb;
    float s = 0.f;
#pragma unroll
    for (int i = 0; i < 4; i++) { v[i] = expf(v[i] - mx); s += v[i]; }
    float bs = blockSum(s);
    __shared__ float sv;
    if (tid == 0) sv = 1.f / bs;
    __syncthreads();
    float inv = sv;
#pragma unroll
    for (int i = 0; i < 4; i++) row[tid + i * 256] = v[i] * inv;
}

// ---------------- residual add + LayerNorm (rows of 2048) ----------------
__global__ void addln_k(const float* __restrict__ a, const float* __restrict__ b,
                        const float* __restrict__ g, const float* __restrict__ be,
                        float* __restrict__ o) {
    int n = blockIdx.x, tid = threadIdx.x;
    const float* pa = a + (size_t)n * DMOD;
    const float* pb = b + (size_t)n * DMOD;
    float x[8];
    float s = 0.f;
#pragma unroll
    for (int i = 0; i < 8; i++) {
        int d = tid + i * 256;
        x[i] = pa[d] + pb[d];
        s += x[i];
    }
    float ts = blockSum(s);
    __shared__ float mu, inv;
    if (tid == 0) mu = ts * (1.f / DMOD);
    __syncthreads();
    float m = mu, vs = 0.f;
#pragma unroll
    for (int i = 0; i < 8; i++) { float dv = x[i] - m; vs += dv * dv; }
    float tv = blockSum(vs);
    if (tid == 0) inv = rsqrtf(tv * (1.f / DMOD) + 1e-5f);
    __syncthreads();
    float iv = inv;
    float* po = o + (size_t)n * DMOD;
#pragma unroll
    for (int i = 0; i < 8; i++) {
        int d = tid + i * 256;
        po[d] = (x[i] - m) * iv * g[d] + be[d];
    }
}

// ---------------- batchnorm (batch stats over N) + relu, per column ----------------
__global__ void bn_k(const float* __restrict__ h, const float* __restrict__ g,
                     const float* __restrict__ b, float* __restrict__ o) {
    int j = blockIdx.x, tid = threadIdx.x;
    float s = 0.f;
    for (int r = tid; r < NTOK; r += 256) s += h[(size_t)r * DECH + j];
    float ts = blockSum(s);
    __shared__ float mu, inv;
    if (tid == 0) mu = ts * (1.f / NTOK);
    __syncthreads();
    float m = mu, vs = 0.f;
    for (int r = tid; r < NTOK; r += 256) { float d = h[(size_t)r * DECH + j] - m; vs += d * d; }
    float tv = blockSum(vs);
    if (tid == 0) inv = rsqrtf(tv * (1.f / NTOK) + 1e-5f);
    __syncthreads();
    float iv = inv, gg = g[j], bb = b[j];
    for (int r = tid; r < NTOK; r += 256) {
        float v = (h[(size_t)r * DECH + j] - m) * iv * gg + bb;
        o[(size_t)r * DECH + j] = fmaxf(v, 0.f);
    }
}

// ---------------- final small GEMM: [1024,1024] @ [1024,35] ----------------
__global__ void dec2_k(const float* __restrict__ hbn, const float* __restrict__ w,
                       const float* __restrict__ b, float* __restrict__ dist) {
    int idx = blockIdx.x * blockDim.x + threadIdx.x;
    if (idx >= NTOK * NCLS1) return;
    int n = idx / NCLS1, c = idx % NCLS1;
    const float* hr = hbn + (size_t)n * DECH;
    float s = 0.f;
    for (int j = 0; j < DECH; j++) s = fmaf(hr[j], w[(size_t)j * NCLS1 + c], s);
    dist[idx] = s + b[c];
}

// ---------------- orchestration ----------------
extern "C" void kernel_launch(void* const* d_in, const int* in_sizes, int n_in,
                              void* d_out, int out_size) {
    const float* feat = (const float*)d_in[0];
    const int*   fid  = (const int*)d_in[1];
    const int*   mn   = (const int*)d_in[2];
    const float* t_aw = (const float*)d_in[3];
    const float* t_ab = (const float*)d_in[4];
    const float* t_lg = (const float*)d_in[5];
    const float* t_lb = (const float*)d_in[6];
    const float* t_w1 = (const float*)d_in[7];
    const float* t_b1 = (const float*)d_in[8];
    const float* t_w2 = (const float*)d_in[9];
    const float* t_b2 = (const float*)d_in[10];
    const float* s_aw = (const float*)d_in[11];
    const float* s_ab = (const float*)d_in[12];
    const float* s_lg = (const float*)d_in[13];
    const float* s_lb = (const float*)d_in[14];
    const float* s_w1 = (const float*)d_in[15];
    const float* s_b1 = (const float*)d_in[16];
    const float* s_w2 = (const float*)d_in[17];
    const float* s_b2 = (const float*)d_in[18];
    const float* dw1  = (const float*)d_in[19];
    const float* db1  = (const float*)d_in[20];
    const float* bng  = (const float*)d_in[21];
    const float* bnb  = (const float*)d_in[22];
    const float* dw2  = (const float*)d_in[23];
    const float* db2  = (const float*)d_in[24];
    float* out = (float*)d_out;

    float* S = nullptr;
    cudaGetSymbolAddress((void**)&S, g_scratch);
    float* sfeat = S + OFF_SFEAT;
    float* qh  = S + OFF_QH;
    float* kh  = S + OFF_KH;
    float* vh  = S + OFF_VH;
    float* ob  = S + OFF_O;
    float* pb  = S + OFF_P;
    float* xb  = S + OFF_X;
    float* fb  = S + OFF_F;
    float* f2b = S + OFF_F2;
    float* c1  = S + OFF_C1;
    float* c2  = S + OFF_C2;
    float* att = S + OFF_ATT;
    float* hd  = S + OFF_HD;
    float* hbn = S + OFF_HBN;

    const size_t DD = (size_t)DMOD * DMOD;

    // 1) selector -> s_feat
    selector_k<<<NTOK, 256>>>(feat, fid, mn, sfeat);

    // 2) encoders
    auto run_enc = [&](const float* x0, const float* kvfix, bool selfattn,
                       const float* aw, const float* ab, const float* lg, const float* lb,
                       const float* w1, const float* b1, const float* w2, const float* b2,
                       float* result) {
        const float* cur = x0;
        for (int l = 0; l < NLAY; l++) {
            const float* kv = selfattn ? cur : kvfix;
            const float* W  = aw + (size_t)l * 4 * DD;
            const float* Bb = ab + (size_t)l * 4 * DMOD;
            // Q, K, V projections -> head-major [H][N][dh]
            tgemm_k<false, 1, false><<<dim3(16, 8, 1), 256>>>(cur, W, Bb, qh,
                DMOD, DMOD, DMOD, 0, 0, 0, 0, 1.f);
            tgemm_k<false, 1, false><<<dim3(16, 8, 1), 256>>>(kv, W + DD, Bb + DMOD, kh,
                DMOD, DMOD, DMOD, 0, 0, 0, 0, 1.f);
            tgemm_k<false, 1, false><<<dim3(16, 8, 1), 256>>>(kv, W + 2 * DD, Bb + 2 * DMOD, vh,
                DMOD, DMOD, DMOD, 0, 0, 0, 0, 1.f);
            // S = Q Kt / sqrt(dh), batched over heads
            tgemm_k<true, 0, false><<<dim3(8, 8, NHEAD), 256>>>(qh, kh, nullptr, att,
                DH, DH, DH, NTOK,
                (long)NTOK * DH, (long)NTOK * DH, (long)NTOK * NTOK, 0.0625f);
            softmax_k<<<NHEAD * NTOK, 256>>>(att);
            // O = att @ V, scatter back to [N, D]
            tgemm_k<false, 2, false><<<dim3(2, 8, NHEAD), 256>>>(att, vh, nullptr, ob,
                NTOK, NTOK, DH, 0,
                (long)NTOK * NTOK, (long)NTOK * DH, 0, 1.f);
            // output projection
            tgemm_k<false, 0, false><<<dim3(16, 8, 1), 256>>>(ob, W + 3 * DD, Bb + 3 * DMOD, pb,
                DMOD, DMOD, DMOD, DMOD, 0, 0, 0, 1.f);
            addln_k<<<NTOK, 256>>>(cur, pb, lg + (size_t)l * 2 * DMOD, lb + (size_t)l * 2 * DMOD, xb);
            // FFN
            tgemm_k<false, 0, true><<<dim3(16, 8, 1), 256>>>(xb, w1 + (size_t)l * DMOD * DFFN,
                b1 + (size_t)l * DFFN, fb,
                DMOD, DMOD, DFFN, DFFN, 0, 0, 0, 1.f);
            tgemm_k<false, 0, false><<<dim3(16, 8, 1), 256>>>(fb, w2 + (size_t)l * DFFN * DMOD,
                b2 + (size_t)l * DMOD, f2b,
                DFFN, DFFN, DMOD, DMOD, 0, 0, 0, 1.f);
            addln_k<<<NTOK, 256>>>(xb, f2b, lg + ((size_t)l * 2 + 1) * DMOD,
                                   lb + ((size_t)l * 2 + 1) * DMOD, result);
            cur = result;
        }
    };

    run_enc(feat, sfeat, false, t_aw, t_ab, t_lg, t_lb, t_w1, t_b1, t_w2, t_b2, c1);
    run_enc(c1, nullptr, true,  s_aw, s_ab, s_lg, s_lb, s_w1, s_b1, s_w2, s_b2, c2);

    // 3) decoder
    tgemm_k<false, 0, false><<<dim3(8, 8, 1), 256>>>(c2, dw1, db1, hd,
        DMOD, DMOD, DECH, DECH, 0, 0, 0, 1.f);
    bn_k<<<DECH, 256>>>(hd, bng, bnb, hbn);
    dec2_k<<<(NTOK * NCLS1 + 255) / 256, 256>>>(hbn, dw2, db2, out + (size_t)NTOK * DMOD);

    // 4) first output: x (spatial encoder output)
    cudaMemcpyAsync(out, c2, (size_t)NTOK * DMOD * sizeof(float),
                    cudaMemcpyDeviceToDevice);
}

// round 5
// speedup vs baseline: 2.4382x; 1.4283x over previous
#include <cuda_runtime.h>
#include <math.h>
#include <stdint.h>

#define NTOK 1024
#define DMOD 2048
#define NHEAD 8
#define DH 256
#define NLAY 3
#define MM 16
#define KSEL 8
#define DFFN 2048
#define DECH 1024
#define NCLS1 35

static constexpr size_t ND_ = (size_t)NTOK * DMOD;
static constexpr size_t OFF_SFEAT = 0, OFF_QH = ND_, OFF_KH = 2*ND_, OFF_VH = 3*ND_,
    OFF_O = 4*ND_, OFF_P = 5*ND_, OFF_X = 6*ND_, OFF_F = 7*ND_, OFF_F2 = 8*ND_,
    OFF_C1 = 9*ND_, OFF_C2 = 10*ND_, OFF_ATT = 11*ND_;
static constexpr size_t OFF_HD  = OFF_ATT + (size_t)NHEAD*NTOK*NTOK;
static constexpr size_t OFF_HBN = OFF_HD + (size_t)NTOK*DECH;
static constexpr size_t SCR_FLOATS = OFF_HBN + (size_t)NTOK*DECH;
__device__ float g_scratch[SCR_FLOATS];

__device__ __forceinline__ float warpSum(float v) {
#pragma unroll
    for (int o = 16; o; o >>= 1) v += __shfl_down_sync(0xffffffffu, v, o);
    return v;
}
__device__ __forceinline__ float warpMax(float v) {
#pragma unroll
    for (int o = 16; o; o >>= 1) v = fmaxf(v, __shfl_down_sync(0xffffffffu, v, o));
    return v;
}
__device__ float blockSum(float v) {
    __shared__ float s[8];
    int lane = threadIdx.x & 31, w = threadIdx.x >> 5;
    v = warpSum(v);
    if (lane == 0) s[w] = v;
    __syncthreads();
    float r = 0.f;
    if (w == 0) { r = (lane < 8) ? s[lane] : 0.f; r = warpSum(r); }
    __syncthreads();
    return r;
}
__device__ float blockMax(float v) {
    __shared__ float s[8];
    int lane = threadIdx.x & 31, w = threadIdx.x >> 5;
    v = warpMax(v);
    if (lane == 0) s[w] = v;
    __syncthreads();
    float r = -1e30f;
    if (w == 0) { r = (lane < 8) ? s[lane] : -1e30f; r = warpMax(r); }
    __syncthreads();
    return r;
}

#define PECOEF (-0.008994473019508232f)

__global__ void selector_k(const float* __restrict__ feat, const int* __restrict__ fid,
                           const int* __restrict__ mn, float* __restrict__ sf) {
    int n = blockIdx.x, tid = threadIdx.x;
    __shared__ int nodes[MM], pos[MM], sel[KSEL];
    __shared__ float sc[MM], wgt[KSEL];
    if (tid < MM) nodes[tid] = mn[n * MM + tid];
    __syncthreads();
    if (tid == 0) {
        int p = 0, prev = fid[nodes[0]];
        pos[0] = 0;
        for (int m = 1; m < MM; m++) {
            int f = fid[nodes[m]];
            if (f != prev) { p++; prev = f; }
            pos[m] = p;
        }
    }
    __syncthreads();
    const float* fn = feat + (size_t)n * DMOD;
    float part[MM];
#pragma unroll
    for (int m = 0; m < MM; m++) part[m] = 0.f;
    for (int d = tid; d < DMOD; d += 256) {
        float fv = fn[d];
        float fr = expf((float)(d >> 1) * PECOEF);
        bool odd = d & 1;
#pragma unroll
        for (int m = 0; m < MM; m++) {
            float ang = (float)pos[m] * fr;
            float pev = odd ? cosf(ang) : sinf(ang);
            part[m] += fv * (feat[(size_t)nodes[m] * DMOD + d] + pev);
        }
    }
    for (int m = 0; m < MM; m++) {
        float ts = blockSum(part[m]);
        if (tid == 0) sc[m] = ts * 0.022097086912079608f;
    }
    __syncthreads();
    if (tid == 0) {
        unsigned used = 0;
        float tv[KSEL];
        for (int k = 0; k < KSEL; k++) {
            float best = -1e30f; int bi = 0;
            for (int m = 0; m < MM; m++)
                if (!((used >> m) & 1) && sc[m] > best) { best = sc[m]; bi = m; }
            used |= 1u << bi; sel[k] = bi; tv[k] = best;
        }
        float mx = tv[0], ssum = 0.f;
        for (int k = 0; k < KSEL; k++) { wgt[k] = expf(tv[k] - mx); ssum += wgt[k]; }
        for (int k = 0; k < KSEL; k++) wgt[k] /= ssum;
    }
    __syncthreads();
    float* po = sf + (size_t)n * DMOD;
    for (int d = tid; d < DMOD; d += 256) {
        float fr = expf((float)(d >> 1) * PECOEF);
        bool odd = d & 1;
        float acc = 0.f;
#pragma unroll
        for (int k = 0; k < KSEL; k++) {
            int m = sel[k];
            float ang = (float)pos[m] * fr;
            float pev = odd ? cosf(ang) : sinf(ang);
            acc += wgt[k] * (feat[(size_t)nodes[m] * DMOD + d] + pev);
        }
        po[d] = acc;
    }
}

// ================= bf16-split tensor GEMM (mma.sync m16n8k16) =================
__device__ __forceinline__ uint32_t smem_u32(const void* p) {
    uint32_t a;
    asm("{ .reg .u64 t; cvta.to.shared.u64 t, %1; cvt.u32.u64 %0, t; }" : "=r"(a) : "l"(p));
    return a;
}
__device__ __forceinline__ float bf_lo(uint32_t w) { return __uint_as_float(w << 16); }
__device__ __forceinline__ float bf_hi(uint32_t w) { return __uint_as_float(w & 0xffff0000u); }
__device__ __forceinline__ uint32_t packbf(float x, float y) {   // lo=x, hi=y
    uint32_t r;
    asm("cvt.rn.satfinite.bf16x2.f32 %0, %1, %2;" : "=r"(r) : "f"(y), "f"(x));
    return r;
}
__device__ __forceinline__ void split2(float x, float y, uint32_t& hi, uint32_t& lo) {
    hi = packbf(x, y);
    lo = packbf(x - bf_lo(hi), y - bf_hi(hi));
}
#define MMA_BF16(c, a, b)                                                     \
    asm volatile(                                                             \
        "mma.sync.aligned.m16n8k16.row.col.f32.bf16.bf16.f32 "                \
        "{%0,%1,%2,%3},{%4,%5,%6,%7},{%8,%9},{%0,%1,%2,%3};\n"                \
        : "+f"(c[0]), "+f"(c[1]), "+f"(c[2]), "+f"(c[3])                      \
        : "r"(a[0]), "r"(a[1]), "r"(a[2]), "r"(a[3]), "r"(b[0]), "r"(b[1]))

__device__ __forceinline__ void cpa16(uint32_t d, const float* s) {
    asm volatile("cp.async.cg.shared.global [%0], [%1], 16;" :: "r"(d), "l"(s));
}
#define CP_COMMIT asm volatile("cp.async.commit_group;")

// smem float layout: A stage0 @0, A stage1 @4608, B stages @9216 (+BS each)
// A tile: [128 rows][36 lead] fp32, rows = M (or N when TB for B)
// B tile TB=0: [32 k-rows][136 lead]
template <bool TB, int OM, bool RELU>
__global__ void __launch_bounds__(256)
bgemm_k(const float* __restrict__ A, const float* __restrict__ B,
        const float* __restrict__ bias, float* __restrict__ C,
        int K, int lda, int ldb, int ldc,
        long sA, long sB, long sC, float scale) {
    constexpr int AS = 4608;
    constexpr int BS = TB ? 4608 : 4352;
    extern __shared__ __align__(16) float sm[];
    int bz = blockIdx.z;
    const float* Ab = A + (long)bz * sA;
    const float* Bb = B + (long)bz * sB;
    int m0 = blockIdx.y * 128, n0 = blockIdx.x * 128;
    int tid = threadIdx.x;
    int warpId = tid >> 5, lane = tid & 31;
    int g = lane >> 2, tig = lane & 3;
    int wm = warpId & 1, wn = warpId >> 1;
    int mBase = wm * 64, nBase = wn * 32;

    uint32_t smb = smem_u32(sm);
    // load thread mapping
    int ar = tid >> 1, ac = (tid & 1) * 16;       // A / B(TB)
    int bk = tid >> 3, bn = (tid & 7) * 16;       // B(!TB)

    auto loadChunk = [&](int ch, int st) {
        int k0 = ch << 5;
        {
            const float* src = Ab + (long)(m0 + ar) * lda + k0 + ac;
            uint32_t dst = smb + (uint32_t)(st * AS + ar * 36 + ac) * 4u;
#pragma unroll
            for (int i = 0; i < 4; i++) cpa16(dst + 16u * i, src + 4 * i);
        }
        if (TB) {
            const float* src = Bb + (long)(n0 + ar) * ldb + k0 + ac;
            uint32_t dst = smb + (uint32_t)(2 * AS + st * BS + ar * 36 + ac) * 4u;
#pragma unroll
            for (int i = 0; i < 4; i++) cpa16(dst + 16u * i, src + 4 * i);
        } else {
            const float* src = Bb + (long)(k0 + bk) * ldb + n0 + bn;
            uint32_t dst = smb + (uint32_t)(2 * AS + st * BS + bk * 136 + bn) * 4u;
#pragma unroll
            for (int i = 0; i < 4; i++) cpa16(dst + 16u * i, src + 4 * i);
        }
        CP_COMMIT;
    };

    float acc[4][4][4];
#pragma unroll
    for (int i = 0; i < 4; i++)
#pragma unroll
        for (int j = 0; j < 4; j++)
#pragma unroll
            for (int r = 0; r < 4; r++) acc[i][j][r] = 0.f;

    int nc = K >> 5;
    loadChunk(0, 0);
    if (nc > 1) loadChunk(1, 1);

    for (int ch = 0; ch < nc; ch++) {
        if (ch + 1 < nc) asm volatile("cp.async.wait_group 1;");
        else             asm volatile("cp.async.wait_group 0;");
        __syncthreads();
        int st = ch & 1;
        const float* Asm = sm + st * AS;
        const float* Bsm = sm + 2 * AS + st * BS;
#pragma unroll
        for (int ks = 0; ks < 2; ks++) {
            int kk = ks * 16 + 2 * tig;
            uint32_t ahi[4][4], alo[4][4], bhi[4][2], blo[4][2];
#pragma unroll
            for (int mi = 0; mi < 4; mi++) {
                int r0 = mBase + mi * 16 + g;
                float2 f0 = *(const float2*)&Asm[r0 * 36 + kk];
                float2 f1 = *(const float2*)&Asm[(r0 + 8) * 36 + kk];
                float2 f2 = *(const float2*)&Asm[r0 * 36 + kk + 8];
                float2 f3 = *(const float2*)&Asm[(r0 + 8) * 36 + kk + 8];
                split2(f0.x, f0.y, ahi[mi][0], alo[mi][0]);
                split2(f1.x, f1.y, ahi[mi][1], alo[mi][1]);
                split2(f2.x, f2.y, ahi[mi][2], alo[mi][2]);
                split2(f3.x, f3.y, ahi[mi][3], alo[mi][3]);
            }
#pragma unroll
            for (int ni = 0; ni < 4; ni++) {
                int c0 = nBase + ni * 8 + g;
                float2 h0, h1;
                if (TB) {
                    h0 = *(const float2*)&Bsm[c0 * 36 + kk];
                    h1 = *(const float2*)&Bsm[c0 * 36 + kk + 8];
                } else {
                    h0.x = Bsm[(kk + 0) * 136 + c0];
                    h0.y = Bsm[(kk + 1) * 136 + c0];
                    h1.x = Bsm[(kk + 8) * 136 + c0];
                    h1.y = Bsm[(kk + 9) * 136 + c0];
                }
                split2(h0.x, h0.y, bhi[ni][0], blo[ni][0]);
                split2(h1.x, h1.y, bhi[ni][1], blo[ni][1]);
            }
#pragma unroll
            for (int mi = 0; mi < 4; mi++)
#pragma unroll
                for (int ni = 0; ni < 4; ni++) {
                    MMA_BF16(acc[mi][ni], ahi[mi], bhi[ni]);
                    MMA_BF16(acc[mi][ni], ahi[mi], blo[ni]);
                    MMA_BF16(acc[mi][ni], alo[mi], bhi[ni]);
                }
        }
        __syncthreads();
        if (ch + 2 < nc) loadChunk(ch + 2, st);
    }

#pragma unroll
    for (int mi = 0; mi < 4; mi++) {
#pragma unroll
        for (int ni = 0; ni < 4; ni++) {
            int row0 = m0 + mBase + mi * 16 + g;
            int col0 = n0 + nBase + ni * 8 + tig * 2;
#pragma unroll
            for (int h = 0; h < 2; h++) {
                int row = row0 + 8 * h;
                float vx = acc[mi][ni][2 * h + 0] * scale;
                float vy = acc[mi][ni][2 * h + 1] * scale;
                if (bias) { vx += bias[col0]; vy += bias[col0 + 1]; }
                if (RELU) { vx = fmaxf(vx, 0.f); vy = fmaxf(vy, 0.f); }
                long idx;
                if (OM == 0)      idx = (long)bz * sC + (long)row * ldc + col0;
                else if (OM == 1) idx = ((long)(col0 >> 8) * NTOK + row) * DH + (col0 & 255);
                else              idx = (long)row * DMOD + (long)bz * DH + col0;
                C[idx] = vx;
                C[idx + 1] = vy;
            }
        }
    }
}

__global__ void softmax_k(float* __restrict__ att) {
    float* row = att + (long)blockIdx.x * 1024;
    int tid = threadIdx.x;
    float v[4], mx = -1e30f;
#pragma unroll
    for (int i = 0; i < 4; i++) { v[i] = row[tid + i * 256]; mx = fmaxf(mx, v[i]); }
    float bm = blockMax(mx);
    __shared__ float sb, sv;
    if (tid == 0) sb = bm;
    __syncthreads();
    mx = sb;
    float s = 0.f;
#pragma unroll
    for (int i = 0; i < 4; i++) { v[i] = expf(v[i] - mx); s += v[i]; }
    float bs = blockSum(s);
    if (tid == 0) sv = 1.f / bs;
    __syncthreads();
#pragma unroll
    for (int i = 0; i < 4; i++) row[tid + i * 256] = v[i] * sv;
}

__global__ void addln_k(const float* __restrict__ a, const float* __restrict__ b,
                        const float* __restrict__ g, const float* __restrict__ be,
                        float* __restrict__ o) {
    int n = blockIdx.x, tid = threadIdx.x;
    const float* pa = a + (size_t)n * DMOD;
    const float* pb = b + (size_t)n * DMOD;
    float x[8], s = 0.f;
#pragma unroll
    for (int i = 0; i < 8; i++) { int d = tid + i * 256; x[i] = pa[d] + pb[d]; s += x[i]; }
    float ts = blockSum(s);
    __shared__ float mu, inv;
    if (tid == 0) mu = ts * (1.f / DMOD);
    __syncthreads();
    float m = mu, vs = 0.f;
#pragma unroll
    for (int i = 0; i < 8; i++) { float dv = x[i] - m; vs += dv * dv; }
    float tv = blockSum(vs);
    if (tid == 0) inv = rsqrtf(tv * (1.f / DMOD) + 1e-5f);
    __syncthreads();
    float iv = inv;
    float* po = o + (size_t)n * DMOD;
#pragma unroll
    for (int i = 0; i < 8; i++) { int d = tid + i * 256; po[d] = (x[i] - m) * iv * g[d] + be[d]; }
}

__global__ void bn_k(const float* __restrict__ h, const float* __restrict__ g,
                     const float* __restrict__ b, float* __restrict__ o) {
    int j = blockIdx.x, tid = threadIdx.x;
    float s = 0.f;
    for (int r = tid; r < NTOK; r += 256) s += h[(size_t)r * DECH + j];
    float ts = blockSum(s);
    __shared__ float mu, inv;
    if (tid == 0) mu = ts * (1.f / NTOK);
    __syncthreads();
    float m = mu, vs = 0.f;
    for (int r = tid; r < NTOK; r += 256) { float d = h[(size_t)r * DECH + j] - m; vs += d * d; }
    float tv = blockSum(vs);
    if (tid == 0) inv = rsqrtf(tv * (1.f / NTOK) + 1e-5f);
    __syncthreads();
    float iv = inv, gg = g[j], bb = b[j];
    for (int r = tid; r < NTOK; r += 256) {
        float v = (h[(size_t)r * DECH + j] - m) * iv * gg + bb;
        o[(size_t)r * DECH + j] = fmaxf(v, 0.f);
    }
}

__global__ void dec2_k(const float* __restrict__ hbn, const float* __restrict__ w,
                       const float* __restrict__ b, float* __restrict__ dist) {
    int idx = blockIdx.x * blockDim.x + threadIdx.x;
    if (idx >= NTOK * NCLS1) return;
    int n = idx / NCLS1, c = idx % NCLS1;
    const float* hr = hbn + (size_t)n * DECH;
    float s = 0.f;
    for (int j = 0; j < DECH; j++) s = fmaf(hr[j], w[(size_t)j * NCLS1 + c], s);
    dist[idx] = s + b[c];
}

// smem bytes per instantiation
#define SMEM_NT 71680   /* TB=0 */
#define SMEM_TT 73728   /* TB=1 */

extern "C" void kernel_launch(void* const* d_in, const int* in_sizes, int n_in,
                              void* d_out, int out_size) {
    const float* feat = (const float*)d_in[0];
    const int* fid = (const int*)d_in[1];
    const int* mn = (const int*)d_in[2];
    const float *t_aw=(const float*)d_in[3], *t_ab=(const float*)d_in[4],
        *t_lg=(const float*)d_in[5], *t_lb=(const float*)d_in[6],
        *t_w1=(const float*)d_in[7], *t_b1=(const float*)d_in[8],
        *t_w2=(const float*)d_in[9], *t_b2=(const float*)d_in[10],
        *s_aw=(const float*)d_in[11], *s_ab=(const float*)d_in[12],
        *s_lg=(const float*)d_in[13], *s_lb=(const float*)d_in[14],
        *s_w1=(const float*)d_in[15], *s_b1=(const float*)d_in[16],
        *s_w2=(const float*)d_in[17], *s_b2=(const float*)d_in[18],
        *dw1=(const float*)d_in[19], *db1=(const float*)d_in[20],
        *bng=(const float*)d_in[21], *bnb=(const float*)d_in[22],
        *dw2=(const float*)d_in[23], *db2=(const float*)d_in[24];
    float* out = (float*)d_out;

    cudaFuncSetAttribute(bgemm_k<false,1,false>, cudaFuncAttributeMaxDynamicSharedMemorySize, SMEM_NT);
    cudaFuncSetAttribute(bgemm_k<true, 0,false>, cudaFuncAttributeMaxDynamicSharedMemorySize, SMEM_TT);
    cudaFuncSetAttribute(bgemm_k<false,2,false>, cudaFuncAttributeMaxDynamicSharedMemorySize, SMEM_NT);
    cudaFuncSetAttribute(bgemm_k<false,0,false>, cudaFuncAttributeMaxDynamicSharedMemorySize, SMEM_NT);
    cudaFuncSetAttribute(bgemm_k<false,0,true>,  cudaFuncAttributeMaxDynamicSharedMemorySize, SMEM_NT);

    float* S = nullptr;
    cudaGetSymbolAddress((void**)&S, g_scratch);
    float *sfeat=S+OFF_SFEAT, *qh=S+OFF_QH, *kh=S+OFF_KH, *vh=S+OFF_VH, *ob=S+OFF_O,
          *pb=S+OFF_P, *xb=S+OFF_X, *fb=S+OFF_F, *f2b=S+OFF_F2, *c1=S+OFF_C1,
          *c2=S+OFF_C2, *att=S+OFF_ATT, *hd=S+OFF_HD, *hbn=S+OFF_HBN;
    const size_t DD = (size_t)DMOD * DMOD;
    const long NDh = (long)NTOK * DH;

    selector_k<<<NTOK, 256>>>(feat, fid, mn, sfeat);

    auto run_enc = [&](const float* x0, const float* kvfix, bool selfa,
                       const float* aw, const float* ab, const float* lg, const float* lb,
                       const float* w1, const float* b1, const float* w2, const float* b2,
                       float* res) {
        const float* cur = x0;
        for (int l = 0; l < NLAY; l++) {
            const float* kv = selfa ? cur : kvfix;
            const float* W = aw + (size_t)l * 4 * DD;
            const float* Bb = ab + (size_t)l * 4 * DMOD;
            bgemm_k<false,1,false><<<dim3(16, 8, 1), 256, SMEM_NT>>>(cur, W, Bb, qh,
                DMOD, DMOD, DMOD, 0, 0, 0, 0, 1.f);
            bgemm_k<false,1,false><<<dim3(16, 8, 1), 256, SMEM_NT>>>(kv, W + DD, Bb + DMOD, kh,
                DMOD, DMOD, DMOD, 0, 0, 0, 0, 1.f);
            bgemm_k<false,1,false><<<dim3(16, 8, 1), 256, SMEM_NT>>>(kv, W + 2 * DD, Bb + 2 * DMOD, vh,
                DMOD, DMOD, DMOD, 0, 0, 0, 0, 1.f);
            bgemm_k<true,0,false><<<dim3(8, 8, NHEAD), 256, SMEM_TT>>>(qh, kh, nullptr, att,
                DH, DH, DH, NTOK, NDh, NDh, (long)NTOK * NTOK, 0.0625f);
            softmax_k<<<NHEAD * NTOK, 256>>>(att);
            bgemm_k<false,2,false><<<dim3(2, 8, NHEAD), 256, SMEM_NT>>>(att, vh, nullptr, ob,
                NTOK, NTOK, DH, 0, (long)NTOK * NTOK, NDh, 0, 1.f);
            bgemm_k<false,0,false><<<dim3(16, 8, 1), 256, SMEM_NT>>>(ob, W + 3 * DD, Bb + 3 * DMOD, pb,
                DMOD, DMOD, DMOD, DMOD, 0, 0, 0, 1.f);
            addln_k<<<NTOK, 256>>>(cur, pb, lg + (size_t)l * 2 * DMOD, lb + (size_t)l * 2 * DMOD, xb);
            bgemm_k<false,0,true><<<dim3(16, 8, 1), 256, SMEM_NT>>>(xb, w1 + (size_t)l * DMOD * DFFN,
                b1 + (size_t)l * DFFN, fb, DMOD, DMOD, DFFN, DFFN, 0, 0, 0, 1.f);
            bgemm_k<false,0,false><<<dim3(16, 8, 1), 256, SMEM_NT>>>(fb, w2 + (size_t)l * DFFN * DMOD,
                b2 + (size_t)l * DMOD, f2b, DFFN, DFFN, DMOD, DMOD, 0, 0, 0, 1.f);
            addln_k<<<NTOK, 256>>>(xb, f2b, lg + ((size_t)l * 2 + 1) * DMOD,
                                   lb + ((size_t)l * 2 + 1) * DMOD, res);
            cur = res;
        }
    };

    run_enc(feat, sfeat, false, t_aw, t_ab, t_lg, t_lb, t_w1, t_b1, t_w2, t_b2, c1);
    run_enc(c1, nullptr, true, s_aw, s_ab, s_lg, s_lb, s_w1, s_b1, s_w2, s_b2, c2);

    bgemm_k<false,0,false><<<dim3(8, 8, 1), 256, SMEM_NT>>>(c2, dw1, db1, hd,
        DMOD, DMOD, DECH, DECH, 0, 0, 0, 1.f);
    bn_k<<<DECH, 256>>>(hd, bng, bnb, hbn);
    dec2_k<<<(NTOK * NCLS1 + 255) / 256, 256>>>(hbn, dw2, db2, out + (size_t)NTOK * DMOD);
    cudaMemcpyAsync(out, c2, (size_t)NTOK * DMOD * sizeof(float), cudaMemcpyDeviceToDevice);
}

// round 6
// speedup vs baseline: 2.8947x; 1.1872x over previous
#include <cuda_runtime.h>
#include <math.h>
#include <stdint.h>

#define NTOK 1024
#define DMOD 2048
#define NHEAD 8
#define DH 256
#define NLAY 3
#define MM 16
#define KSEL 8
#define DFFN 2048
#define DECH 1024
#define NCLS1 35

static constexpr size_t ND_ = (size_t)NTOK * DMOD;
static constexpr size_t OFF_SFEAT = 0, OFF_QH = ND_, OFF_KH = 2*ND_, OFF_VH = 3*ND_,
    OFF_O = 4*ND_, OFF_P = 5*ND_, OFF_X = 6*ND_, OFF_F = 7*ND_, OFF_F2 = 8*ND_,
    OFF_C1 = 9*ND_, OFF_C2 = 10*ND_, OFF_ATT = 11*ND_;
static constexpr size_t OFF_HD  = OFF_ATT + (size_t)NHEAD*NTOK*NTOK;
static constexpr size_t OFF_HBN = OFF_HD + (size_t)NTOK*DECH;
static constexpr size_t SCR_FLOATS = OFF_HBN + (size_t)NTOK*DECH;
__device__ float g_scratch[SCR_FLOATS];

__device__ __forceinline__ float warpSum(float v) {
#pragma unroll
    for (int o = 16; o; o >>= 1) v += __shfl_down_sync(0xffffffffu, v, o);
    return v;
}
__device__ __forceinline__ float warpMax(float v) {
#pragma unroll
    for (int o = 16; o; o >>= 1) v = fmaxf(v, __shfl_down_sync(0xffffffffu, v, o));
    return v;
}
__device__ float blockSum(float v) {
    __shared__ float s[8];
    int lane = threadIdx.x & 31, w = threadIdx.x >> 5;
    v = warpSum(v);
    if (lane == 0) s[w] = v;
    __syncthreads();
    float r = 0.f;
    if (w == 0) { r = (lane < 8) ? s[lane] : 0.f; r = warpSum(r); }
    __syncthreads();
    return r;
}
__device__ float blockMax(float v) {
    __shared__ float s[8];
    int lane = threadIdx.x & 31, w = threadIdx.x >> 5;
    v = warpMax(v);
    if (lane == 0) s[w] = v;
    __syncthreads();
    float r = -1e30f;
    if (w == 0) { r = (lane < 8) ? s[lane] : -1e30f; r = warpMax(r); }
    __syncthreads();
    return r;
}

#define PECOEF (-0.008994473019508232f)

__global__ void selector_k(const float* __restrict__ feat, const int* __restrict__ fid,
                           const int* __restrict__ mn, float* __restrict__ sf) {
    int n = blockIdx.x, tid = threadIdx.x;
    __shared__ int nodes[MM], pos[MM], sel[KSEL];
    __shared__ float sc[MM], wgt[KSEL];
    if (tid < MM) nodes[tid] = mn[n * MM + tid];
    __syncthreads();
    if (tid == 0) {
        int p = 0, prev = fid[nodes[0]];
        pos[0] = 0;
        for (int m = 1; m < MM; m++) {
            int f = fid[nodes[m]];
            if (f != prev) { p++; prev = f; }
            pos[m] = p;
        }
    }
    __syncthreads();
    const float* fn = feat + (size_t)n * DMOD;
    float part[MM];
#pragma unroll
    for (int m = 0; m < MM; m++) part[m] = 0.f;
    for (int d = tid; d < DMOD; d += 256) {
        float fv = fn[d];
        float fr = expf((float)(d >> 1) * PECOEF);
        bool odd = d & 1;
#pragma unroll
        for (int m = 0; m < MM; m++) {
            float ang = (float)pos[m] * fr;
            float pev = odd ? cosf(ang) : sinf(ang);
            part[m] += fv * (feat[(size_t)nodes[m] * DMOD + d] + pev);
        }
    }
    for (int m = 0; m < MM; m++) {
        float ts = blockSum(part[m]);
        if (tid == 0) sc[m] = ts * 0.022097086912079608f;
    }
    __syncthreads();
    if (tid == 0) {
        unsigned used = 0;
        float tv[KSEL];
        for (int k = 0; k < KSEL; k++) {
            float best = -1e30f; int bi = 0;
            for (int m = 0; m < MM; m++)
                if (!((used >> m) & 1) && sc[m] > best) { best = sc[m]; bi = m; }
            used |= 1u << bi; sel[k] = bi; tv[k] = best;
        }
        float mx = tv[0], ssum = 0.f;
        for (int k = 0; k < KSEL; k++) { wgt[k] = expf(tv[k] - mx); ssum += wgt[k]; }
        for (int k = 0; k < KSEL; k++) wgt[k] /= ssum;
    }
    __syncthreads();
    float* po = sf + (size_t)n * DMOD;
    for (int d = tid; d < DMOD; d += 256) {
        float fr = expf((float)(d >> 1) * PECOEF);
        bool odd = d & 1;
        float acc = 0.f;
#pragma unroll
        for (int k = 0; k < KSEL; k++) {
            int m = sel[k];
            float ang = (float)pos[m] * fr;
            float pev = odd ? cosf(ang) : sinf(ang);
            acc += wgt[k] * (feat[(size_t)nodes[m] * DMOD + d] + pev);
        }
        po[d] = acc;
    }
}

// ================= bf16-split GEMM: split at fill, ldmatrix fragments =================
__device__ __forceinline__ uint32_t smem_u32(const void* p) {
    uint32_t a;
    asm("{ .reg .u64 t; cvta.to.shared.u64 t, %1; cvt.u32.u64 %0, t; }" : "=r"(a) : "l"(p));
    return a;
}
__device__ __forceinline__ float bf_lo(uint32_t w) { return __uint_as_float(w << 16); }
__device__ __forceinline__ float bf_hi(uint32_t w) { return __uint_as_float(w & 0xffff0000u); }
__device__ __forceinline__ uint32_t packbf(float x, float y) {   // low half=bf16(x), high=bf16(y)
    uint32_t r;
    asm("cvt.rn.satfinite.bf16x2.f32 %0, %1, %2;" : "=r"(r) : "f"(y), "f"(x));
    return r;
}
__device__ __forceinline__ void split2(float x, float y, uint32_t& hi, uint32_t& lo) {
    hi = packbf(x, y);
    lo = packbf(x - bf_lo(hi), y - bf_hi(hi));
}
__device__ __forceinline__ void sts128(uint32_t a, uint32_t x, uint32_t y, uint32_t z, uint32_t w) {
    asm volatile("st.shared.v4.b32 [%0], {%1,%2,%3,%4};" :: "r"(a), "r"(x), "r"(y), "r"(z), "r"(w) : "memory");
}
__device__ __forceinline__ void sts32(uint32_t a, uint32_t x) {
    asm volatile("st.shared.b32 [%0], %1;" :: "r"(a), "r"(x) : "memory");
}
#define LDMX4(r0, r1, r2, r3, ad)                                             \
    asm volatile("ldmatrix.sync.aligned.m8n8.x4.shared.b16 {%0,%1,%2,%3}, [%4];" \
                 : "=r"(r0), "=r"(r1), "=r"(r2), "=r"(r3) : "r"(ad))
#define MMA_BF16(c, a, b)                                                     \
    asm volatile(                                                             \
        "mma.sync.aligned.m16n8k16.row.col.f32.bf16.bf16.f32 "                \
        "{%0,%1,%2,%3},{%4,%5,%6,%7},{%8,%9},{%0,%1,%2,%3};\n"                \
        : "+f"(c[0]), "+f"(c[1]), "+f"(c[2]), "+f"(c[3])                      \
        : "r"(a[0]), "r"(a[1]), "r"(a[2]), "r"(a[3]), "r"(b[0]), "r"(b[1]))

// smem bytes: per stage 40960 (A_hi 0, A_lo 10240, B_hi 20480, B_lo 30720), 2 stages
// tile rows stride 80 bytes (40 bf16): 20-word stride -> conflict-free ldmatrix
#define SMEM_BG 81920

template <bool TB, int OM, bool RELU>
__global__ void __launch_bounds__(256)
bgemm_k(const float* __restrict__ A, const float* __restrict__ B,
        const float* __restrict__ bias, float* __restrict__ C,
        int K, int lda, int ldb, int ldc,
        long sA, long sB, long sC, float scale) {
    extern __shared__ __align__(16) char sm8[];
    int bz = blockIdx.z;
    const float* Ab = A + (long)bz * sA;
    const float* Bb = B + (long)bz * sB;
    int m0 = blockIdx.y * 128, n0 = blockIdx.x * 128;
    int tid = threadIdx.x;
    int warpId = tid >> 5, lane = tid & 31;
    int g = lane >> 2, tig = lane & 3;
    int wm = warpId & 1, wn = warpId >> 1;
    int mBase = wm * 64, nBase = wn * 32;
    uint32_t smb = smem_u32(sm8);

    int arow = tid >> 1, akh = (tid & 1) * 16;   // A fill (and B fill when TB)
    int bkp = tid & 15, bnj = tid >> 4;          // B fill (!TB): k-pair, n-octet

    float4 la[4], lb[4];
    auto ldgChunk = [&](int ch) {
        int k0 = ch << 5;
        const float4* ap = (const float4*)(Ab + (long)(m0 + arow) * lda + k0 + akh);
        la[0] = ap[0]; la[1] = ap[1]; la[2] = ap[2]; la[3] = ap[3];
        if (TB) {
            const float4* bp = (const float4*)(Bb + (long)(n0 + arow) * ldb + k0 + akh);
            lb[0] = bp[0]; lb[1] = bp[1]; lb[2] = bp[2]; lb[3] = bp[3];
        } else {
            const float4* bp = (const float4*)(Bb + (long)(k0 + 2 * bkp) * ldb + n0 + bnj * 8);
            lb[0] = bp[0]; lb[1] = bp[1];
            const float4* bp2 = (const float4*)(Bb + (long)(k0 + 2 * bkp + 1) * ldb + n0 + bnj * 8);
            lb[2] = bp2[0]; lb[3] = bp2[1];
        }
    };
    auto stsChunk = [&](int st) {
        uint32_t sb = smb + (uint32_t)st * 40960u;
        uint32_t hi[8], lo[8];
        const float* fa = (const float*)la;
#pragma unroll
        for (int i = 0; i < 8; i++) split2(fa[2 * i], fa[2 * i + 1], hi[i], lo[i]);
        uint32_t aoff = sb + (uint32_t)(arow * 80 + akh * 2);
        sts128(aoff,           hi[0], hi[1], hi[2], hi[3]);
        sts128(aoff + 16u,     hi[4], hi[5], hi[6], hi[7]);
        sts128(aoff + 10240u,      lo[0], lo[1], lo[2], lo[3]);
        sts128(aoff + 10240u + 16u, lo[4], lo[5], lo[6], lo[7]);
        const float* fb = (const float*)lb;
        if (TB) {
#pragma unroll
            for (int i = 0; i < 8; i++) split2(fb[2 * i], fb[2 * i + 1], hi[i], lo[i]);
            uint32_t boff = sb + 20480u + (uint32_t)(arow * 80 + akh * 2);
            sts128(boff,           hi[0], hi[1], hi[2], hi[3]);
            sts128(boff + 16u,     hi[4], hi[5], hi[6], hi[7]);
            sts128(boff + 10240u,      lo[0], lo[1], lo[2], lo[3]);
            sts128(boff + 10240u + 16u, lo[4], lo[5], lo[6], lo[7]);
        } else {
#pragma unroll
            for (int n = 0; n < 8; n++) {
                uint32_t h, l;
                split2(fb[n], fb[8 + n], h, l);
                uint32_t boff = sb + 20480u + (uint32_t)((bnj * 8 + n) * 80 + bkp * 4);
                sts32(boff, h);
                sts32(boff + 10240u, l);
            }
        }
    };

    float acc[4][4][4];
#pragma unroll
    for (int i = 0; i < 4; i++)
#pragma unroll
        for (int j = 0; j < 4; j++)
#pragma unroll
            for (int r = 0; r < 4; r++) acc[i][j][r] = 0.f;

    int lrow = lane & 7, lgrp = lane >> 3;
    auto compute = [&](int st) {
        uint32_t sb = smb + (uint32_t)st * 40960u;
#pragma unroll
        for (int ks = 0; ks < 2; ks++) {
            uint32_t ahi[4][4], alo[4][4], bhi[4][2], blo[4][2];
            int kbA = ks * 32 + (lgrp >> 1) * 16;
            int rA = (lgrp & 1) * 8 + lrow;
#pragma unroll
            for (int mi = 0; mi < 4; mi++) {
                uint32_t ad = sb + (uint32_t)((mBase + mi * 16 + rA) * 80 + kbA);
                LDMX4(ahi[mi][0], ahi[mi][1], ahi[mi][2], ahi[mi][3], ad);
                LDMX4(alo[mi][0], alo[mi][1], alo[mi][2], alo[mi][3], ad + 10240u);
            }
            int kbB = ks * 32 + (lgrp & 1) * 16;
            int rB = (lgrp >> 1) * 8 + lrow;
#pragma unroll
            for (int np = 0; np < 2; np++) {
                uint32_t bd = sb + 20480u + (uint32_t)((nBase + np * 16 + rB) * 80 + kbB);
                LDMX4(bhi[2*np][0], bhi[2*np][1], bhi[2*np+1][0], bhi[2*np+1][1], bd);
                LDMX4(blo[2*np][0], blo[2*np][1], blo[2*np+1][0], blo[2*np+1][1], bd + 10240u);
            }
#pragma unroll
            for (int mi = 0; mi < 4; mi++)
#pragma unroll
                for (int ni = 0; ni < 4; ni++) {
                    MMA_BF16(acc[mi][ni], ahi[mi], bhi[ni]);
                    MMA_BF16(acc[mi][ni], ahi[mi], blo[ni]);
                    MMA_BF16(acc[mi][ni], alo[mi], bhi[ni]);
                }
        }
    };

    int nc = K >> 5;
    ldgChunk(0);
    stsChunk(0);
    __syncthreads();
    for (int ch = 0; ch < nc; ch++) {
        if (ch + 1 < nc) ldgChunk(ch + 1);
        compute(ch & 1);
        __syncthreads();
        if (ch + 1 < nc) {
            stsChunk((ch + 1) & 1);
            __syncthreads();
        }
    }

#pragma unroll
    for (int mi = 0; mi < 4; mi++) {
#pragma unroll
        for (int ni = 0; ni < 4; ni++) {
            int row0 = m0 + mBase + mi * 16 + g;
            int col0 = n0 + nBase + ni * 8 + tig * 2;
#pragma unroll
            for (int h = 0; h < 2; h++) {
                int row = row0 + 8 * h;
                float vx = acc[mi][ni][2 * h + 0] * scale;
                float vy = acc[mi][ni][2 * h + 1] * scale;
                if (bias) { vx += bias[col0]; vy += bias[col0 + 1]; }
                if (RELU) { vx = fmaxf(vx, 0.f); vy = fmaxf(vy, 0.f); }
                long idx;
                if (OM == 0)      idx = (long)bz * sC + (long)row * ldc + col0;
                else if (OM == 1) idx = ((long)(col0 >> 8) * NTOK + row) * DH + (col0 & 255);
                else              idx = (long)row * DMOD + (long)bz * DH + col0;
                C[idx] = vx;
                C[idx + 1] = vy;
            }
        }
    }
}

__global__ void softmax_k(float* __restrict__ att) {
    float* row = att + (long)blockIdx.x * 1024;
    int tid = threadIdx.x;
    float v[4], mx = -1e30f;
#pragma unroll
    for (int i = 0; i < 4; i++) { v[i] = row[tid + i * 256]; mx = fmaxf(mx, v[i]); }
    float bm = blockMax(mx);
    __shared__ float sb, sv;
    if (tid == 0) sb = bm;
    __syncthreads();
    mx = sb;
    float s = 0.f;
#pragma unroll
    for (int i = 0; i < 4; i++) { v[i] = expf(v[i] - mx); s += v[i]; }
    float bs = blockSum(s);
    if (tid == 0) sv = 1.f / bs;
    __syncthreads();
#pragma unroll
    for (int i = 0; i < 4; i++) row[tid + i * 256] = v[i] * sv;
}

__global__ void addln_k(const float* __restrict__ a, const float* __restrict__ b,
                        const float* __restrict__ g, const float* __restrict__ be,
                        float* __restrict__ o) {
    int n = blockIdx.x, tid = threadIdx.x;
    const float* pa = a + (size_t)n * DMOD;
    const float* pb = b + (size_t)n * DMOD;
    float x[8], s = 0.f;
#pragma unroll
    for (int i = 0; i < 8; i++) { int d = tid + i * 256; x[i] = pa[d] + pb[d]; s += x[i]; }
    float ts = blockSum(s);
    __shared__ float mu, inv;
    if (tid == 0) mu = ts * (1.f / DMOD);
    __syncthreads();
    float m = mu, vs = 0.f;
#pragma unroll
    for (int i = 0; i < 8; i++) { float dv = x[i] - m; vs += dv * dv; }
    float tv = blockSum(vs);
    if (tid == 0) inv = rsqrtf(tv * (1.f / DMOD) + 1e-5f);
    __syncthreads();
    float iv = inv;
    float* po = o + (size_t)n * DMOD;
#pragma unroll
    for (int i = 0; i < 8; i++) { int d = tid + i * 256; po[d] = (x[i] - m) * iv * g[d] + be[d]; }
}

__global__ void bn_k(const float* __restrict__ h, const float* __restrict__ g,
                     const float* __restrict__ b, float* __restrict__ o) {
    int j = blockIdx.x, tid = threadIdx.x;
    float s = 0.f;
    for (int r = tid; r < NTOK; r += 256) s += h[(size_t)r * DECH + j];
    float ts = blockSum(s);
    __shared__ float mu, inv;
    if (tid == 0) mu = ts * (1.f / NTOK);
    __syncthreads();
    float m = mu, vs = 0.f;
    for (int r = tid; r < NTOK; r += 256) { float d = h[(size_t)r * DECH + j] - m; vs += d * d; }
    float tv = blockSum(vs);
    if (tid == 0) inv = rsqrtf(tv * (1.f / NTOK) + 1e-5f);
    __syncthreads();
    float iv = inv, gg = g[j], bb = b[j];
    for (int r = tid; r < NTOK; r += 256) {
        float v = (h[(size_t)r * DECH + j] - m) * iv * gg + bb;
        o[(size_t)r * DECH + j] = fmaxf(v, 0.f);
    }
}

__global__ void dec2_k(const float* __restrict__ hbn, const float* __restrict__ w,
                       const float* __restrict__ b, float* __restrict__ dist) {
    int idx = blockIdx.x * blockDim.x + threadIdx.x;
    if (idx >= NTOK * NCLS1) return;
    int n = idx / NCLS1, c = idx % NCLS1;
    const float* hr = hbn + (size_t)n * DECH;
    float s = 0.f;
    for (int j = 0; j < DECH; j++) s = fmaf(hr[j], w[(size_t)j * NCLS1 + c], s);
    dist[idx] = s + b[c];
}

extern "C" void kernel_launch(void* const* d_in, const int* in_sizes, int n_in,
                              void* d_out, int out_size) {
    const float* feat = (const float*)d_in[0];
    const int* fid = (const int*)d_in[1];
    const int* mn = (const int*)d_in[2];
    const float *t_aw=(const float*)d_in[3], *t_ab=(const float*)d_in[4],
        *t_lg=(const float*)d_in[5], *t_lb=(const float*)d_in[6],
        *t_w1=(const float*)d_in[7], *t_b1=(const float*)d_in[8],
        *t_w2=(const float*)d_in[9], *t_b2=(const float*)d_in[10],
        *s_aw=(const float*)d_in[11], *s_ab=(const float*)d_in[12],
        *s_lg=(const float*)d_in[13], *s_lb=(const float*)d_in[14],
        *s_w1=(const float*)d_in[15], *s_b1=(const float*)d_in[16],
        *s_w2=(const float*)d_in[17], *s_b2=(const float*)d_in[18],
        *dw1=(const float*)d_in[19], *db1=(const float*)d_in[20],
        *bng=(const float*)d_in[21], *bnb=(const float*)d_in[22],
        *dw2=(const float*)d_in[23], *db2=(const float*)d_in[24];
    float* out = (float*)d_out;

    cudaFuncSetAttribute(bgemm_k<false,1,false>, cudaFuncAttributeMaxDynamicSharedMemorySize, SMEM_BG);
    cudaFuncSetAttribute(bgemm_k<true, 0,false>, cudaFuncAttributeMaxDynamicSharedMemorySize, SMEM_BG);
    cudaFuncSetAttribute(bgemm_k<false,2,false>, cudaFuncAttributeMaxDynamicSharedMemorySize, SMEM_BG);
    cudaFuncSetAttribute(bgemm_k<false,0,false>, cudaFuncAttributeMaxDynamicSharedMemorySize, SMEM_BG);
    cudaFuncSetAttribute(bgemm_k<false,0,true>,  cudaFuncAttributeMaxDynamicSharedMemorySize, SMEM_BG);

    float* S = nullptr;
    cudaGetSymbolAddress((void**)&S, g_scratch);
    float *sfeat=S+OFF_SFEAT, *qh=S+OFF_QH, *kh=S+OFF_KH, *vh=S+OFF_VH, *ob=S+OFF_O,
          *pb=S+OFF_P, *xb=S+OFF_X, *fb=S+OFF_F, *f2b=S+OFF_F2, *c1=S+OFF_C1,
          *c2=S+OFF_C2, *att=S+OFF_ATT, *hd=S+OFF_HD, *hbn=S+OFF_HBN;
    const size_t DD = (size_t)DMOD * DMOD;
    const long NDh = (long)NTOK * DH;

    selector_k<<<NTOK, 256>>>(feat, fid, mn, sfeat);

    auto run_enc = [&](const float* x0, const float* kvfix, bool selfa,
                       const float* aw, const float* ab, const float* lg, const float* lb,
                       const float* w1, const float* b1, const float* w2, const float* b2,
                       float* res) {
        const float* cur = x0;
        for (int l = 0; l < NLAY; l++) {
            const float* kv = selfa ? cur : kvfix;
            const float* W = aw + (size_t)l * 4 * DD;
            const float* Bb = ab + (size_t)l * 4 * DMOD;
            bgemm_k<false,1,false><<<dim3(16, 8, 1), 256, SMEM_BG>>>(cur, W, Bb, qh,
                DMOD, DMOD, DMOD, 0, 0, 0, 0, 1.f);
            bgemm_k<false,1,false><<<dim3(16, 8, 1), 256, SMEM_BG>>>(kv, W + DD, Bb + DMOD, kh,
                DMOD, DMOD, DMOD, 0, 0, 0, 0, 1.f);
            bgemm_k<false,1,false><<<dim3(16, 8, 1), 256, SMEM_BG>>>(kv, W + 2 * DD, Bb + 2 * DMOD, vh,
                DMOD, DMOD, DMOD, 0, 0, 0, 0, 1.f);
            bgemm_k<true,0,false><<<dim3(8, 8, NHEAD), 256, SMEM_BG>>>(qh, kh, nullptr, att,
                DH, DH, DH, NTOK, NDh, NDh, (long)NTOK * NTOK, 0.0625f);
            softmax_k<<<NHEAD * NTOK, 256>>>(att);
            bgemm_k<false,2,false><<<dim3(2, 8, NHEAD), 256, SMEM_BG>>>(att, vh, nullptr, ob,
                NTOK, NTOK, DH, 0, (long)NTOK * NTOK, NDh, 0, 1.f);
            bgemm_k<false,0,false><<<dim3(16, 8, 1), 256, SMEM_BG>>>(ob, W + 3 * DD, Bb + 3 * DMOD, pb,
                DMOD, DMOD, DMOD, DMOD, 0, 0, 0, 1.f);
            addln_k<<<NTOK, 256>>>(cur, pb, lg + (size_t)l * 2 * DMOD, lb + (size_t)l * 2 * DMOD, xb);
            bgemm_k<false,0,true><<<dim3(16, 8, 1), 256, SMEM_BG>>>(xb, w1 + (size_t)l * DMOD * DFFN,
                b1 + (size_t)l * DFFN, fb, DMOD, DMOD, DFFN, DFFN, 0, 0, 0, 1.f);
            bgemm_k<false,0,false><<<dim3(16, 8, 1), 256, SMEM_BG>>>(fb, w2 + (size_t)l * DFFN * DMOD,
                b2 + (size_t)l * DMOD, f2b, DFFN, DFFN, DMOD, DMOD, 0, 0, 0, 1.f);
            addln_k<<<NTOK, 256>>>(xb, f2b, lg + ((size_t)l * 2 + 1) * DMOD,
                                   lb + ((size_t)l * 2 + 1) * DMOD, res);
            cur = res;
        }
    };

    run_enc(feat, sfeat, false, t_aw, t_ab, t_lg, t_lb, t_w1, t_b1, t_w2, t_b2, c1);
    run_enc(c1, nullptr, true, s_aw, s_ab, s_lg, s_lb, s_w1, s_b1, s_w2, s_b2, c2);

    bgemm_k<false,0,false><<<dim3(8, 8, 1), 256, SMEM_BG>>>(c2, dw1, db1, hd,
        DMOD, DMOD, DECH, DECH, 0, 0, 0, 1.f);
    bn_k<<<DECH, 256>>>(hd, bng, bnb, hbn);
    dec2_k<<<(NTOK * NCLS1 + 255) / 256, 256>>>(hbn, dw2, db2, out + (size_t)NTOK * DMOD);
    cudaMemcpyAsync(out, c2, (size_t)NTOK * DMOD * sizeof(float), cudaMemcpyDeviceToDevice);
}